// round 4
// baseline (speedup 1.0000x reference)
#include <cuda_runtime.h>
#include <math.h>

#define DIM     1024
#define HEADS   16
#define DHEAD   64
#define INNER   1024   // HEADS*DHEAD
#define SEQ     1024
#define BATCH   8
#define ROWS    (BATCH*SEQ)   // 8192

// Scratch (allocation-free rule: __device__ globals)
__device__ float g_xn [ROWS * DIM];        // 32 MB : layernormed x
__device__ float g_qkv[ROWS * 3 * INNER];  // 96 MB : qkv (q,k rms-normed in place)
__device__ float g_att[ROWS * INNER];      // 32 MB : attention out, [b n (h d)]

// ---------------------------------------------------------------------------
// LayerNorm: one block (256 threads) per row of 1024
// ---------------------------------------------------------------------------
__global__ __launch_bounds__(256) void ln_kernel(const float* __restrict__ x,
                                                 const float* __restrict__ gamma,
                                                 float* __restrict__ out)
{
    int row = blockIdx.x;
    const float4* xr = (const float4*)(x + (size_t)row * DIM);
    float4 v = xr[threadIdx.x];
    float s  = v.x + v.y + v.z + v.w;
    float ss = v.x*v.x + v.y*v.y + v.z*v.z + v.w*v.w;

    #pragma unroll
    for (int o = 16; o > 0; o >>= 1) {
        s  += __shfl_down_sync(0xffffffffu, s,  o);
        ss += __shfl_down_sync(0xffffffffu, ss, o);
    }
    __shared__ float sh_s[8], sh_ss[8];
    int w = threadIdx.x >> 5, lane = threadIdx.x & 31;
    if (lane == 0) { sh_s[w] = s; sh_ss[w] = ss; }
    __syncthreads();
    if (w == 0) {
        s  = (lane < 8) ? sh_s[lane]  : 0.f;
        ss = (lane < 8) ? sh_ss[lane] : 0.f;
        #pragma unroll
        for (int o = 4; o > 0; o >>= 1) {
            s  += __shfl_down_sync(0xffffffffu, s,  o);
            ss += __shfl_down_sync(0xffffffffu, ss, o);
        }
        if (lane == 0) { sh_s[0] = s; sh_ss[0] = ss; }
    }
    __syncthreads();
    float mu  = sh_s[0]  * (1.0f / DIM);
    float var = sh_ss[0] * (1.0f / DIM) - mu * mu;
    float inv = rsqrtf(var + 1e-5f);
    float4 g = ((const float4*)gamma)[threadIdx.x];
    float4 r;
    r.x = (v.x - mu) * inv * g.x;
    r.y = (v.y - mu) * inv * g.y;
    r.z = (v.z - mu) * inv * g.z;
    r.w = (v.w - mu) * inv * g.w;
    ((float4*)(out + (size_t)row * DIM))[threadIdx.x] = r;
}

// ---------------------------------------------------------------------------
// SGEMM: C[M,N] = A[M,K] * B[K,N], all row-major. 128x128x16 tiles, 256 thr,
// 8x8 micro-tile. M%128==0, N%128==0, K%16==0 (true for all our shapes).
// ---------------------------------------------------------------------------
__global__ __launch_bounds__(256) void sgemm128(const float* __restrict__ A,
                                                const float* __restrict__ B,
                                                float* __restrict__ C,
                                                int M, int N, int K)
{
    __shared__ float As[16][128];
    __shared__ float Bs[16][128];

    int tid  = threadIdx.x;
    int brow = blockIdx.y * 128;
    int bcol = blockIdx.x * 128;
    int tx = tid & 15;          // 0..15  -> 8 cols each
    int ty = tid >> 4;          // 0..15  -> 8 rows each

    int a_row = tid >> 2;           // 0..63
    int a_col = (tid & 3) << 2;     // 0,4,8,12
    int b_row = tid >> 5;           // 0..7
    int b_col = (tid & 31) << 2;    // 0..124

    float acc[8][8];
    #pragma unroll
    for (int i = 0; i < 8; i++)
        #pragma unroll
        for (int j = 0; j < 8; j++) acc[i][j] = 0.f;

    for (int k0 = 0; k0 < K; k0 += 16) {
        #pragma unroll
        for (int r = 0; r < 2; r++) {
            int row = a_row + r * 64;
            float4 t = *(const float4*)(A + (size_t)(brow + row) * K + k0 + a_col);
            As[a_col + 0][row] = t.x;
            As[a_col + 1][row] = t.y;
            As[a_col + 2][row] = t.z;
            As[a_col + 3][row] = t.w;
        }
        #pragma unroll
        for (int r = 0; r < 2; r++) {
            int row = b_row + r * 8;
            *(float4*)&Bs[row][b_col] =
                *(const float4*)(B + (size_t)(k0 + row) * N + bcol + b_col);
        }
        __syncthreads();

        #pragma unroll
        for (int k = 0; k < 16; k++) {
            float af[8], bf[8];
            #pragma unroll
            for (int i = 0; i < 8; i++) af[i] = As[k][ty * 8 + i];
            #pragma unroll
            for (int j = 0; j < 8; j++) bf[j] = Bs[k][tx * 8 + j];
            #pragma unroll
            for (int i = 0; i < 8; i++)
                #pragma unroll
                for (int j = 0; j < 8; j++) acc[i][j] += af[i] * bf[j];
        }
        __syncthreads();
    }

    #pragma unroll
    for (int i = 0; i < 8; i++) {
        float* cp = C + (size_t)(brow + ty * 8 + i) * N + bcol + tx * 8;
        *(float4*)(cp + 0) = make_float4(acc[i][0], acc[i][1], acc[i][2], acc[i][3]);
        *(float4*)(cp + 4) = make_float4(acc[i][4], acc[i][5], acc[i][6], acc[i][7]);
    }
}

// ---------------------------------------------------------------------------
// Per-head RMS norm on q and k segments of qkv, in place.
// One block (512 threads) per row: 32 units (16 heads x {q,k}), 16 lanes/unit.
// ---------------------------------------------------------------------------
__global__ __launch_bounds__(512) void rms_kernel(float* __restrict__ qkv,
                                                  const float* __restrict__ qg,
                                                  const float* __restrict__ kg)
{
    int row    = blockIdx.x;
    int unit   = threadIdx.x >> 4;   // 0..31
    int lane16 = threadIdx.x & 15;
    int qk     = unit >> 4;          // 0 = q, 1 = k
    int head   = unit & 15;

    float* p = qkv + (size_t)row * (3 * INNER) + qk * INNER + head * DHEAD;
    float4 v = ((float4*)p)[lane16];
    float ss = v.x*v.x + v.y*v.y + v.z*v.z + v.w*v.w;
    #pragma unroll
    for (int o = 8; o > 0; o >>= 1)
        ss += __shfl_xor_sync(0xffffffffu, ss, o, 16);
    float n = sqrtf(ss);
    float scale = 8.0f / fmaxf(n, 1e-12f);   // sqrt(64) = 8

    const float* g = (qk ? kg : qg) + head * DHEAD + lane16 * 4;
    v.x *= scale * g[0];
    v.y *= scale * g[1];
    v.z *= scale * g[2];
    v.w *= scale * g[3];
    ((float4*)p)[lane16] = v;
}

// ---------------------------------------------------------------------------
// Flash-style attention. Block = 128 threads = 128 query rows for one (b,h).
// grid = (128 bh, 8 q-tiles). K/V tiles (32x64) staged in SMEM; q row and o
// accumulator in registers; online softmax in sub-chunks of 8 keys.
// Writes out in [b n (h d)] layout directly.
// ---------------------------------------------------------------------------
__global__ __launch_bounds__(128) void attn_kernel(const float* __restrict__ qkv,
                                                   float* __restrict__ out)
{
    const int BN = 32;
    int bh = blockIdx.x;             // 0..127
    int b  = bh >> 4, h = bh & 15;
    int row = blockIdx.y * 128 + threadIdx.x;   // query row in [0,1024)
    size_t base = (size_t)b * SEQ * (3 * INNER);

    float q[64], o[64];
    {
        const float4* qp = (const float4*)(qkv + base + (size_t)row * (3 * INNER) + h * DHEAD);
        #pragma unroll
        for (int i = 0; i < 16; i++) {
            float4 t = qp[i];
            q[4*i+0] = t.x; q[4*i+1] = t.y; q[4*i+2] = t.z; q[4*i+3] = t.w;
        }
    }
    #pragma unroll
    for (int d = 0; d < 64; d++) o[d] = 0.f;
    float m = -INFINITY, l = 0.f;

    __shared__ float ks[BN][DHEAD];
    __shared__ float vs[BN][DHEAD];

    for (int n0 = 0; n0 < SEQ; n0 += BN) {
        __syncthreads();
        // cooperative load: BN*64 floats = 512 float4 per tile, 128 threads -> 4 each
        #pragma unroll
        for (int i = 0; i < 4; i++) {
            int idx = threadIdx.x + i * 128;   // 0..511
            int r = idx >> 4, c = idx & 15;
            const float* kp = qkv + base + (size_t)(n0 + r) * (3 * INNER) + INNER + h * DHEAD;
            const float* vp = qkv + base + (size_t)(n0 + r) * (3 * INNER) + 2 * INNER + h * DHEAD;
            ((float4*)&ks[r][0])[c] = ((const float4*)kp)[c];
            ((float4*)&vs[r][0])[c] = ((const float4*)vp)[c];
        }
        __syncthreads();

        #pragma unroll
        for (int j0 = 0; j0 < BN; j0 += 8) {
            float s[8];
            #pragma unroll
            for (int j = 0; j < 8; j++) {
                float acc = 0.f;
                #pragma unroll
                for (int d = 0; d < 64; d++) acc += q[d] * ks[j0 + j][d];
                s[j] = acc;
            }
            float mt = s[0];
            #pragma unroll
            for (int j = 1; j < 8; j++) mt = fmaxf(mt, s[j]);
            float mnew = fmaxf(m, mt);
            float alpha = __expf(m - mnew);   // 0 on first pass (m = -inf)
            l *= alpha;
            #pragma unroll
            for (int d = 0; d < 64; d++) o[d] *= alpha;
            #pragma unroll
            for (int j = 0; j < 8; j++) {
                float p = __expf(s[j] - mnew);
                l += p;
                #pragma unroll
                for (int d = 0; d < 64; d++) o[d] += p * vs[j0 + j][d];
            }
            m = mnew;
        }
    }

    float invl = 1.0f / l;
    float4* op = (float4*)(out + (size_t)(b * SEQ + row) * INNER + h * DHEAD);
    #pragma unroll
    for (int i = 0; i < 16; i++)
        op[i] = make_float4(o[4*i+0]*invl, o[4*i+1]*invl, o[4*i+2]*invl, o[4*i+3]*invl);
}

// ---------------------------------------------------------------------------
extern "C" void kernel_launch(void* const* d_in, const int* in_sizes, int n_in,
                              void* d_out, int out_size)
{
    const float* x     = (const float*)d_in[0];
    const float* ln_g  = (const float*)d_in[1];
    const float* q_g   = (const float*)d_in[2];
    const float* k_g   = (const float*)d_in[3];
    const float* w_qkv = (const float*)d_in[4];
    const float* w_out = (const float*)d_in[5];
    float* out = (float*)d_out;

    float *xn, *qkv, *att;
    cudaGetSymbolAddress((void**)&xn,  g_xn);
    cudaGetSymbolAddress((void**)&qkv, g_qkv);
    cudaGetSymbolAddress((void**)&att, g_att);

    ln_kernel<<<ROWS, 256>>>(x, ln_g, xn);

    sgemm128<<<dim3(3 * INNER / 128, ROWS / 128), 256>>>(xn, w_qkv, qkv,
                                                         ROWS, 3 * INNER, DIM);

    rms_kernel<<<ROWS, 512>>>(qkv, q_g, k_g);

    attn_kernel<<<dim3(BATCH * HEADS, SEQ / 128), 128>>>(qkv, att);

    sgemm128<<<dim3(DIM / 128, ROWS / 128), 256>>>(att, w_out, out,
                                                   ROWS, DIM, INNER);
}

// round 10
// speedup vs baseline: 1.0696x; 1.0696x over previous
#include <cuda_runtime.h>
#include <math.h>
#include <stdint.h>

#define DIM     1024
#define HEADS   16
#define DHEAD   64
#define INNER   1024
#define SEQ     1024
#define BATCH   8
#define ROWS    (BATCH*SEQ)   // 8192

// Scratch (allocation-free rule: __device__ globals)
__device__ float g_xn [ROWS * DIM];
__device__ float g_qkv[ROWS * 3 * INNER];
__device__ float g_att[ROWS * INNER];

__device__ __forceinline__ uint32_t f2tf32(float x) {
    uint32_t u;
    asm("cvt.rna.tf32.f32 %0, %1;" : "=r"(u) : "f"(x));
    return u;
}
// 3xTF32 split: x = hi + lo (both representable in tf32)
__device__ __forceinline__ void tf32_split(float x, uint32_t& hi, uint32_t& lo) {
    hi = f2tf32(x);
    lo = f2tf32(x - __uint_as_float(hi));
}

// ===========================================================================
// 3xTF32 mma.sync GEMM: C[M,N] = A[M,K] * B[K,N], row-major, fp32-accurate.
// 128x128x32 CTA tile, 256 threads (8 warps, 2x4), 64x32 warp tile.
// SMEM holds fp32; hi/lo tf32 split happens at fragment load.
// acc += a_lo*b_hi + a_hi*b_lo + a_hi*b_hi  (error ~2^-22)
// ===========================================================================
#define SSTRIDE 36

__global__ __launch_bounds__(256, 2) void gemm_tf32x3(const float* __restrict__ A,
                                                      const float* __restrict__ B,
                                                      float* __restrict__ C,
                                                      int M, int N, int K)
{
    __shared__ float As[128 * SSTRIDE];
    __shared__ float Bs[128 * SSTRIDE];

    const int tid  = threadIdx.x;
    const int lane = tid & 31;
    const int wid  = tid >> 5;
    const int mw   = wid >> 2;          // 0..1  (64-row slab)
    const int nw   = wid & 3;           // 0..3  (32-col slab)
    const int brow = blockIdx.y * 128;
    const int bcol = blockIdx.x * 128;

    const int gr = lane >> 2;           // 0..7
    const int gc = lane & 3;            // 0..3

    float acc[4][4][4];
    #pragma unroll
    for (int i = 0; i < 4; i++)
        #pragma unroll
        for (int j = 0; j < 4; j++)
            #pragma unroll
            for (int c = 0; c < 4; c++) acc[i][j][c] = 0.f;

    const int b_k  = tid & 31;
    const int b_ng = tid >> 5;

    for (int k0 = 0; k0 < K; k0 += 32) {
        // ---- A tile [128][32] fp32 ----
        #pragma unroll
        for (int j = 0; j < 4; j++) {
            int linear = tid + j * 256;
            int row = linear >> 3;
            int c4  = linear & 7;
            float4 v = *(const float4*)(A + (size_t)(brow + row) * K + k0 + c4 * 4);
            *(float4*)&As[row * SSTRIDE + c4 * 4] = v;
        }
        // ---- B tile [32][128] -> Bs[n][k] transposed, fp32 ----
        #pragma unroll
        for (int j = 0; j < 4; j++) {
            int n4 = b_ng + j * 8;
            float4 v = *(const float4*)(B + (size_t)(k0 + b_k) * N + bcol + n4 * 4);
            Bs[(n4 * 4 + 0) * SSTRIDE + b_k] = v.x;
            Bs[(n4 * 4 + 1) * SSTRIDE + b_k] = v.y;
            Bs[(n4 * 4 + 2) * SSTRIDE + b_k] = v.z;
            Bs[(n4 * 4 + 3) * SSTRIDE + b_k] = v.w;
        }
        __syncthreads();

        #pragma unroll
        for (int ks = 0; ks < 4; ks++) {
            const int kk = ks * 8;
            // B fragments (hi+lo) for all 4 ni
            uint32_t bh[4][2], bl[4][2];
            #pragma unroll
            for (int ni = 0; ni < 4; ni++) {
                int nb = nw * 32 + ni * 8;
                const float* p = &Bs[(nb + gr) * SSTRIDE + kk + gc];
                tf32_split(p[0], bh[ni][0], bl[ni][0]);
                tf32_split(p[4], bh[ni][1], bl[ni][1]);
            }
            #pragma unroll
            for (int mi = 0; mi < 4; mi++) {
                int mb = mw * 64 + mi * 16;
                const float* p0 = &As[(mb + gr)     * SSTRIDE + kk + gc];
                const float* p1 = &As[(mb + 8 + gr) * SSTRIDE + kk + gc];
                uint32_t ah[4], al[4];
                tf32_split(p0[0], ah[0], al[0]);
                tf32_split(p1[0], ah[1], al[1]);
                tf32_split(p0[4], ah[2], al[2]);
                tf32_split(p1[4], ah[3], al[3]);
                #pragma unroll
                for (int ni = 0; ni < 4; ni++) {
                    float* c = acc[mi][ni];
                    asm volatile(
                        "mma.sync.aligned.m16n8k8.row.col.f32.tf32.tf32.f32 "
                        "{%0,%1,%2,%3}, {%4,%5,%6,%7}, {%8,%9}, {%0,%1,%2,%3};"
                        : "+f"(c[0]), "+f"(c[1]), "+f"(c[2]), "+f"(c[3])
                        : "r"(al[0]), "r"(al[1]), "r"(al[2]), "r"(al[3]),
                          "r"(bh[ni][0]), "r"(bh[ni][1]));
                    asm volatile(
                        "mma.sync.aligned.m16n8k8.row.col.f32.tf32.tf32.f32 "
                        "{%0,%1,%2,%3}, {%4,%5,%6,%7}, {%8,%9}, {%0,%1,%2,%3};"
                        : "+f"(c[0]), "+f"(c[1]), "+f"(c[2]), "+f"(c[3])
                        : "r"(ah[0]), "r"(ah[1]), "r"(ah[2]), "r"(ah[3]),
                          "r"(bl[ni][0]), "r"(bl[ni][1]));
                    asm volatile(
                        "mma.sync.aligned.m16n8k8.row.col.f32.tf32.tf32.f32 "
                        "{%0,%1,%2,%3}, {%4,%5,%6,%7}, {%8,%9}, {%0,%1,%2,%3};"
                        : "+f"(c[0]), "+f"(c[1]), "+f"(c[2]), "+f"(c[3])
                        : "r"(ah[0]), "r"(ah[1]), "r"(ah[2]), "r"(ah[3]),
                          "r"(bh[ni][0]), "r"(bh[ni][1]));
                }
            }
        }
        __syncthreads();
    }

    // ---- Epilogue ----
    #pragma unroll
    for (int mi = 0; mi < 4; mi++) {
        int row = brow + mw * 64 + mi * 16 + gr;
        #pragma unroll
        for (int ni = 0; ni < 4; ni++) {
            int col = bcol + nw * 32 + ni * 8 + gc * 2;
            *(float2*)(C + (size_t)row * N + col) =
                make_float2(acc[mi][ni][0], acc[mi][ni][1]);
            *(float2*)(C + (size_t)(row + 8) * N + col) =
                make_float2(acc[mi][ni][2], acc[mi][ni][3]);
        }
    }
}

// ===========================================================================
// LayerNorm: one block (256 threads) per row of 1024
// ===========================================================================
__global__ __launch_bounds__(256) void ln_kernel(const float* __restrict__ x,
                                                 const float* __restrict__ gamma,
                                                 float* __restrict__ out)
{
    int row = blockIdx.x;
    const float4* xr = (const float4*)(x + (size_t)row * DIM);
    float4 v = xr[threadIdx.x];
    float s  = v.x + v.y + v.z + v.w;
    float ss = v.x*v.x + v.y*v.y + v.z*v.z + v.w*v.w;
    #pragma unroll
    for (int o = 16; o > 0; o >>= 1) {
        s  += __shfl_down_sync(0xffffffffu, s,  o);
        ss += __shfl_down_sync(0xffffffffu, ss, o);
    }
    __shared__ float sh_s[8], sh_ss[8];
    int w = threadIdx.x >> 5, lane = threadIdx.x & 31;
    if (lane == 0) { sh_s[w] = s; sh_ss[w] = ss; }
    __syncthreads();
    if (w == 0) {
        s  = (lane < 8) ? sh_s[lane]  : 0.f;
        ss = (lane < 8) ? sh_ss[lane] : 0.f;
        #pragma unroll
        for (int o = 4; o > 0; o >>= 1) {
            s  += __shfl_down_sync(0xffffffffu, s,  o);
            ss += __shfl_down_sync(0xffffffffu, ss, o);
        }
        if (lane == 0) { sh_s[0] = s; sh_ss[0] = ss; }
    }
    __syncthreads();
    float mu  = sh_s[0]  * (1.0f / DIM);
    float var = sh_ss[0] * (1.0f / DIM) - mu * mu;
    float inv = rsqrtf(var + 1e-5f);
    float4 g = ((const float4*)gamma)[threadIdx.x];
    float4 r;
    r.x = (v.x - mu) * inv * g.x;
    r.y = (v.y - mu) * inv * g.y;
    r.z = (v.z - mu) * inv * g.z;
    r.w = (v.w - mu) * inv * g.w;
    ((float4*)(out + (size_t)row * DIM))[threadIdx.x] = r;
}

// ===========================================================================
// Per-head RMS on q,k in place
// ===========================================================================
__global__ __launch_bounds__(512) void rms_kernel(float* __restrict__ qkv,
                                                  const float* __restrict__ qg,
                                                  const float* __restrict__ kg)
{
    int row    = blockIdx.x;
    int unit   = threadIdx.x >> 4;
    int lane16 = threadIdx.x & 15;
    int qk     = unit >> 4;
    int head   = unit & 15;

    float* p = qkv + (size_t)row * (3 * INNER) + qk * INNER + head * DHEAD;
    float4 v = ((float4*)p)[lane16];
    float ss = v.x*v.x + v.y*v.y + v.z*v.z + v.w*v.w;
    #pragma unroll
    for (int o = 8; o > 0; o >>= 1)
        ss += __shfl_xor_sync(0xffffffffu, ss, o, 16);
    float n = sqrtf(ss);
    float scale = 8.0f / fmaxf(n, 1e-12f);

    const float* g = (qk ? kg : qg) + head * DHEAD + lane16 * 4;
    v.x *= scale * g[0];
    v.y *= scale * g[1];
    v.z *= scale * g[2];
    v.w *= scale * g[3];
    ((float4*)p)[lane16] = v;
}

// ===========================================================================
// Flash attention (SIMT fp32, float4-vectorized SMEM reads)
// ===========================================================================
__global__ __launch_bounds__(128) void attn_kernel(const float* __restrict__ qkv,
                                                   float* __restrict__ out)
{
    const int BN = 32;
    int bh = blockIdx.x;
    int b  = bh >> 4, h = bh & 15;
    int row = blockIdx.y * 128 + threadIdx.x;
    size_t base = (size_t)b * SEQ * (3 * INNER);

    float q[64], o[64];
    {
        const float4* qp = (const float4*)(qkv + base + (size_t)row * (3 * INNER) + h * DHEAD);
        #pragma unroll
        for (int i = 0; i < 16; i++) {
            float4 t = qp[i];
            q[4*i+0] = t.x; q[4*i+1] = t.y; q[4*i+2] = t.z; q[4*i+3] = t.w;
        }
    }
    #pragma unroll
    for (int d = 0; d < 64; d++) o[d] = 0.f;
    float m = -INFINITY, l = 0.f;

    __shared__ float ks[BN][DHEAD];
    __shared__ float vs[BN][DHEAD];

    for (int n0 = 0; n0 < SEQ; n0 += BN) {
        __syncthreads();
        #pragma unroll
        for (int i = 0; i < 4; i++) {
            int idx = threadIdx.x + i * 128;
            int r = idx >> 4, c = idx & 15;
            const float* kp = qkv + base + (size_t)(n0 + r) * (3 * INNER) + INNER + h * DHEAD;
            const float* vp = qkv + base + (size_t)(n0 + r) * (3 * INNER) + 2 * INNER + h * DHEAD;
            ((float4*)&ks[r][0])[c] = ((const float4*)kp)[c];
            ((float4*)&vs[r][0])[c] = ((const float4*)vp)[c];
        }
        __syncthreads();

        #pragma unroll
        for (int j0 = 0; j0 < BN; j0 += 8) {
            float s[8];
            #pragma unroll
            for (int j = 0; j < 8; j++) {
                const float4* kr = (const float4*)&ks[j0 + j][0];
                float acc = 0.f;
                #pragma unroll
                for (int d4 = 0; d4 < 16; d4++) {
                    float4 k4 = kr[d4];
                    acc += q[4*d4+0]*k4.x + q[4*d4+1]*k4.y
                         + q[4*d4+2]*k4.z + q[4*d4+3]*k4.w;
                }
                s[j] = acc;
            }
            float mt = s[0];
            #pragma unroll
            for (int j = 1; j < 8; j++) mt = fmaxf(mt, s[j]);
            float mnew = fmaxf(m, mt);
            float alpha = __expf(m - mnew);
            l *= alpha;
            #pragma unroll
            for (int d = 0; d < 64; d++) o[d] *= alpha;
            #pragma unroll
            for (int j = 0; j < 8; j++) {
                float p = __expf(s[j] - mnew);
                l += p;
                const float4* vr = (const float4*)&vs[j0 + j][0];
                #pragma unroll
                for (int d4 = 0; d4 < 16; d4++) {
                    float4 v4 = vr[d4];
                    o[4*d4+0] += p * v4.x;
                    o[4*d4+1] += p * v4.y;
                    o[4*d4+2] += p * v4.z;
                    o[4*d4+3] += p * v4.w;
                }
            }
            m = mnew;
        }
    }

    float invl = 1.0f / l;
    float4* op = (float4*)(out + (size_t)(b * SEQ + row) * INNER + h * DHEAD);
    #pragma unroll
    for (int i = 0; i < 16; i++)
        op[i] = make_float4(o[4*i+0]*invl, o[4*i+1]*invl, o[4*i+2]*invl, o[4*i+3]*invl);
}

// ===========================================================================
extern "C" void kernel_launch(void* const* d_in, const int* in_sizes, int n_in,
                              void* d_out, int out_size)
{
    const float* x     = (const float*)d_in[0];
    const float* ln_g  = (const float*)d_in[1];
    const float* q_g   = (const float*)d_in[2];
    const float* k_g   = (const float*)d_in[3];
    const float* w_qkv = (const float*)d_in[4];
    const float* w_out = (const float*)d_in[5];
    float* out = (float*)d_out;

    float *xn, *qkv, *att;
    cudaGetSymbolAddress((void**)&xn,  g_xn);
    cudaGetSymbolAddress((void**)&qkv, g_qkv);
    cudaGetSymbolAddress((void**)&att, g_att);

    ln_kernel<<<ROWS, 256>>>(x, ln_g, xn);

    gemm_tf32x3<<<dim3(3 * INNER / 128, ROWS / 128), 256>>>(xn, w_qkv, qkv,
                                                            ROWS, 3 * INNER, DIM);

    rms_kernel<<<ROWS, 512>>>(qkv, q_g, k_g);

    attn_kernel<<<dim3(BATCH * HEADS, SEQ / 128), 128>>>(qkv, att);

    gemm_tf32x3<<<dim3(DIM / 128, ROWS / 128), 256>>>(att, w_out, out,
                                                      ROWS, DIM, INNER);
}

// round 12
// speedup vs baseline: 2.1141x; 1.9766x over previous
#include <cuda_runtime.h>
#include <cuda_fp16.h>
#include <math.h>
#include <stdint.h>

#define DIM     1024
#define HEADS   16
#define DHEAD   64
#define INNER   1024
#define SEQ     1024
#define BATCH   8
#define ROWS    (BATCH*SEQ)   // 8192

// Scratch (allocation-free rule: __device__ globals)
__device__ float g_xn [ROWS * DIM];
__device__ float g_qkv[ROWS * 3 * INNER];
__device__ float g_att[ROWS * INNER];

// ---------------------------------------------------------------------------
// helpers: fp16 hi/lo split (3xFP16 error compensation)
// ---------------------------------------------------------------------------
__device__ __forceinline__ uint32_t pack2(float x, float y) {
    __half2 h = __floats2half2_rn(x, y);          // .x = low half
    return *reinterpret_cast<uint32_t*>(&h);
}
__device__ __forceinline__ void split2(float x, float y, uint32_t& hi, uint32_t& lo) {
    float hx = __half2float(__float2half_rn(x));
    float hy = __half2float(__float2half_rn(y));
    hi = pack2(hx, hy);
    lo = pack2(x - hx, y - hy);
}

#define MMA_F16(c, A0, A1, A2, A3, B0, B1)                                    \
    asm volatile("mma.sync.aligned.m16n8k16.row.col.f32.f16.f16.f32 "         \
                 "{%0,%1,%2,%3}, {%4,%5,%6,%7}, {%8,%9}, {%0,%1,%2,%3};"      \
                 : "+f"((c)[0]), "+f"((c)[1]), "+f"((c)[2]), "+f"((c)[3])     \
                 : "r"(A0), "r"(A1), "r"(A2), "r"(A3), "r"(B0), "r"(B1))

// ===========================================================================
// 3xFP16 mma GEMM: C[M,N] = A[M,K]*B[K,N], row-major. 128x128x32 CTA tile,
// 256 thr (8 warps, 2x4), 64x32 warp tile. SMEM holds pre-split hi/lo halves.
// Row stride = 40 halves (20 b32): fragment reads bank-conflict-free.
// ===========================================================================
#define ASTR 20   // b32 per row (32 halves data + 8 pad)

__global__ __launch_bounds__(256, 2) void gemm_f16x3(const float* __restrict__ A,
                                                     const float* __restrict__ B,
                                                     float* __restrict__ C,
                                                     int M, int N, int K)
{
    __shared__ __align__(16) uint32_t Ahi[128 * ASTR];
    __shared__ __align__(16) uint32_t Alo[128 * ASTR];
    __shared__ __align__(16) uint32_t Bhi[128 * ASTR];
    __shared__ __align__(16) uint32_t Blo[128 * ASTR];

    const int tid  = threadIdx.x;
    const int lane = tid & 31;
    const int wid  = tid >> 5;
    const int mw   = wid >> 2;
    const int nw   = wid & 3;
    const int brow = blockIdx.y * 128;
    const int bcol = blockIdx.x * 128;
    const int gr   = lane >> 2;
    const int gc   = lane & 3;

    float acc[4][4][4];
    #pragma unroll
    for (int i = 0; i < 4; i++)
        #pragma unroll
        for (int j = 0; j < 4; j++)
            #pragma unroll
            for (int c = 0; c < 4; c++) acc[i][j][c] = 0.f;

    const int b_k  = tid & 31;
    const int b_ng = tid >> 5;

    for (int k0 = 0; k0 < K; k0 += 32) {
        // ---- A fill: 128x32, split once, store (hi,lo) pairs ----
        #pragma unroll
        for (int j = 0; j < 4; j++) {
            int linear = tid + j * 256;
            int row = linear >> 3;
            int c4  = linear & 7;
            float4 v = *(const float4*)(A + (size_t)(brow + row) * K + k0 + c4 * 4);
            uint32_t h0, l0, h1, l1;
            split2(v.x, v.y, h0, l0);
            split2(v.z, v.w, h1, l1);
            int idx = row * ASTR + c4 * 2;
            *(uint2*)&Ahi[idx] = make_uint2(h0, h1);
            *(uint2*)&Alo[idx] = make_uint2(l0, l1);
        }
        // ---- B fill: 32x128 -> Bs[n][k] transposed halves ----
        #pragma unroll
        for (int j = 0; j < 4; j++) {
            int n4 = b_ng + j * 8;
            float4 v = *(const float4*)(B + (size_t)(k0 + b_k) * N + bcol + n4 * 4);
            float vv[4] = {v.x, v.y, v.z, v.w};
            #pragma unroll
            for (int c = 0; c < 4; c++) {
                __half hh = __float2half_rn(vv[c]);
                __half hl = __float2half_rn(vv[c] - __half2float(hh));
                int hidx = (n4 * 4 + c) * (ASTR * 2) + b_k;
                reinterpret_cast<__half*>(Bhi)[hidx] = hh;
                reinterpret_cast<__half*>(Blo)[hidx] = hl;
            }
        }
        __syncthreads();

        #pragma unroll
        for (int ks = 0; ks < 2; ks++) {
            uint32_t bh[4][2], bl[4][2];
            #pragma unroll
            for (int ni = 0; ni < 4; ni++) {
                int n  = nw * 32 + ni * 8 + gr;
                int bi = n * ASTR + ks * 8 + gc;
                bh[ni][0] = Bhi[bi]; bh[ni][1] = Bhi[bi + 4];
                bl[ni][0] = Blo[bi]; bl[ni][1] = Blo[bi + 4];
            }
            #pragma unroll
            for (int mi = 0; mi < 4; mi++) {
                int r   = mw * 64 + mi * 16 + gr;
                int ai  = r * ASTR + ks * 8 + gc;
                int ai8 = ai + 8 * ASTR;
                uint32_t ah0 = Ahi[ai],  ah1 = Ahi[ai8];
                uint32_t ah2 = Ahi[ai + 4], ah3 = Ahi[ai8 + 4];
                uint32_t al0 = Alo[ai],  al1 = Alo[ai8];
                uint32_t al2 = Alo[ai + 4], al3 = Alo[ai8 + 4];
                #pragma unroll
                for (int ni = 0; ni < 4; ni++) {
                    MMA_F16(acc[mi][ni], al0, al1, al2, al3, bh[ni][0], bh[ni][1]);
                    MMA_F16(acc[mi][ni], ah0, ah1, ah2, ah3, bl[ni][0], bl[ni][1]);
                    MMA_F16(acc[mi][ni], ah0, ah1, ah2, ah3, bh[ni][0], bh[ni][1]);
                }
            }
        }
        __syncthreads();
    }

    #pragma unroll
    for (int mi = 0; mi < 4; mi++) {
        int row = brow + mw * 64 + mi * 16 + gr;
        #pragma unroll
        for (int ni = 0; ni < 4; ni++) {
            int col = bcol + nw * 32 + ni * 8 + gc * 2;
            *(float2*)(C + (size_t)row * N + col) =
                make_float2(acc[mi][ni][0], acc[mi][ni][1]);
            *(float2*)(C + (size_t)(row + 8) * N + col) =
                make_float2(acc[mi][ni][2], acc[mi][ni][3]);
        }
    }
}

// ===========================================================================
// LayerNorm
// ===========================================================================
__global__ __launch_bounds__(256) void ln_kernel(const float* __restrict__ x,
                                                 const float* __restrict__ gamma,
                                                 float* __restrict__ out)
{
    int row = blockIdx.x;
    const float4* xr = (const float4*)(x + (size_t)row * DIM);
    float4 v = xr[threadIdx.x];
    float s  = v.x + v.y + v.z + v.w;
    float ss = v.x*v.x + v.y*v.y + v.z*v.z + v.w*v.w;
    #pragma unroll
    for (int o = 16; o > 0; o >>= 1) {
        s  += __shfl_down_sync(0xffffffffu, s,  o);
        ss += __shfl_down_sync(0xffffffffu, ss, o);
    }
    __shared__ float sh_s[8], sh_ss[8];
    int w = threadIdx.x >> 5, lane = threadIdx.x & 31;
    if (lane == 0) { sh_s[w] = s; sh_ss[w] = ss; }
    __syncthreads();
    if (w == 0) {
        s  = (lane < 8) ? sh_s[lane]  : 0.f;
        ss = (lane < 8) ? sh_ss[lane] : 0.f;
        #pragma unroll
        for (int o = 4; o > 0; o >>= 1) {
            s  += __shfl_down_sync(0xffffffffu, s,  o);
            ss += __shfl_down_sync(0xffffffffu, ss, o);
        }
        if (lane == 0) { sh_s[0] = s; sh_ss[0] = ss; }
    }
    __syncthreads();
    float mu  = sh_s[0]  * (1.0f / DIM);
    float var = sh_ss[0] * (1.0f / DIM) - mu * mu;
    float inv = rsqrtf(var + 1e-5f);
    float4 g = ((const float4*)gamma)[threadIdx.x];
    float4 r;
    r.x = (v.x - mu) * inv * g.x;
    r.y = (v.y - mu) * inv * g.y;
    r.z = (v.z - mu) * inv * g.z;
    r.w = (v.w - mu) * inv * g.w;
    ((float4*)(out + (size_t)row * DIM))[threadIdx.x] = r;
}

// ===========================================================================
// Per-head RMS on q,k in place
// ===========================================================================
__global__ __launch_bounds__(512) void rms_kernel(float* __restrict__ qkv,
                                                  const float* __restrict__ qg,
                                                  const float* __restrict__ kg)
{
    int row    = blockIdx.x;
    int unit   = threadIdx.x >> 4;
    int lane16 = threadIdx.x & 15;
    int qk     = unit >> 4;
    int head   = unit & 15;

    float* p = qkv + (size_t)row * (3 * INNER) + qk * INNER + head * DHEAD;
    float4 v = ((float4*)p)[lane16];
    float ss = v.x*v.x + v.y*v.y + v.z*v.z + v.w*v.w;
    #pragma unroll
    for (int o = 8; o > 0; o >>= 1)
        ss += __shfl_xor_sync(0xffffffffu, ss, o, 16);
    float n = sqrtf(ss);
    float scale = 8.0f / fmaxf(n, 1e-12f);

    const float* g = (qk ? kg : qg) + head * DHEAD + lane16 * 4;
    v.x *= scale * g[0];
    v.y *= scale * g[1];
    v.z *= scale * g[2];
    v.w *= scale * g[3];
    ((float4*)p)[lane16] = v;
}

// ===========================================================================
// MMA flash attention (FA-2): 256 thr, 8 warps x 16 q-rows = 128 q / CTA.
// 64-key tiles; S = Q K^T and O += P V via 3xFP16 mma; register softmax.
// K tile stored [key][d], V tile transposed [d][key], hi/lo halves,
// row stride 72 halves (36 b32) -> conflict-free fragment reads.
// ===========================================================================
#define KSTR 36   // b32 per row (64 halves data + 8 pad)

__global__ __launch_bounds__(256) void attn_mma(const float* __restrict__ qkv,
                                                float* __restrict__ out)
{
    __shared__ __align__(16) uint32_t Khi[64 * KSTR];
    __shared__ __align__(16) uint32_t Klo[64 * KSTR];
    __shared__ __align__(16) uint32_t Vhi[64 * KSTR];
    __shared__ __align__(16) uint32_t Vlo[64 * KSTR];

    const int tid  = threadIdx.x;
    const int lane = tid & 31;
    const int wid  = tid >> 5;
    const int gr   = lane >> 2;
    const int gc   = lane & 3;

    const int bh = blockIdx.x;
    const int b  = bh >> 4, h = bh & 15;
    const int q0 = blockIdx.y * 128 + wid * 16;
    const size_t base = (size_t)b * SEQ * (3 * INNER);
    const float* qp = qkv + base + h * DHEAD;

    // ---- Q fragments (hi/lo), 16 rows x 64 d per warp, kept in registers ----
    uint32_t qhi[4][4], qlo[4][4];
    #pragma unroll
    for (int ks = 0; ks < 4; ks++) {
        int r0 = q0 + gr, r1 = q0 + 8 + gr;
        int d0 = ks * 16 + 2 * gc, d1 = d0 + 8;
        float2 x00 = *(const float2*)(qp + (size_t)r0 * (3 * INNER) + d0);
        float2 x10 = *(const float2*)(qp + (size_t)r1 * (3 * INNER) + d0);
        float2 x01 = *(const float2*)(qp + (size_t)r0 * (3 * INNER) + d1);
        float2 x11 = *(const float2*)(qp + (size_t)r1 * (3 * INNER) + d1);
        split2(x00.x, x00.y, qhi[ks][0], qlo[ks][0]);
        split2(x10.x, x10.y, qhi[ks][1], qlo[ks][1]);
        split2(x01.x, x01.y, qhi[ks][2], qlo[ks][2]);
        split2(x11.x, x11.y, qhi[ks][3], qlo[ks][3]);
    }

    float oacc[8][4];
    #pragma unroll
    for (int i = 0; i < 8; i++)
        #pragma unroll
        for (int c = 0; c < 4; c++) oacc[i][c] = 0.f;
    float m0 = -INFINITY, m1 = -INFINITY, l0 = 0.f, l1 = 0.f;

    for (int n0 = 0; n0 < SEQ; n0 += 64) {
        __syncthreads();
        // ---- K/V tile fill (64 keys x 64 d), split to hi/lo halves ----
        #pragma unroll
        for (int j = 0; j < 4; j++) {
            int linear = tid + j * 256;
            int key = linear >> 4, d4 = linear & 15;
            const float* kp = qkv + base + (size_t)(n0 + key) * (3 * INNER)
                              + INNER + h * DHEAD + d4 * 4;
            float4 kv = *(const float4*)kp;
            uint32_t h0, l0u, h1, l1u;
            split2(kv.x, kv.y, h0, l0u);
            split2(kv.z, kv.w, h1, l1u);
            int idx = key * KSTR + d4 * 2;
            *(uint2*)&Khi[idx] = make_uint2(h0, h1);
            *(uint2*)&Klo[idx] = make_uint2(l0u, l1u);

            float4 vv = *(const float4*)(kp + INNER);
            float va[4] = {vv.x, vv.y, vv.z, vv.w};
            #pragma unroll
            for (int c = 0; c < 4; c++) {
                int d = d4 * 4 + c;
                __half hh = __float2half_rn(va[c]);
                int hidx = d * (KSTR * 2) + key;
                reinterpret_cast<__half*>(Vhi)[hidx] = hh;
                reinterpret_cast<__half*>(Vlo)[hidx] =
                    __float2half_rn(va[c] - __half2float(hh));
            }
        }
        __syncthreads();

        // ---- S = Q K^T (16 x 64 per warp), 3xFP16 ----
        float sacc[8][4];
        #pragma unroll
        for (int i = 0; i < 8; i++)
            #pragma unroll
            for (int c = 0; c < 4; c++) sacc[i][c] = 0.f;

        #pragma unroll
        for (int ks = 0; ks < 4; ks++) {
            #pragma unroll
            for (int ni = 0; ni < 8; ni++) {
                int bi = (ni * 8 + gr) * KSTR + ks * 8 + gc;
                uint32_t kh0 = Khi[bi], kh1 = Khi[bi + 4];
                uint32_t kl0 = Klo[bi], kl1 = Klo[bi + 4];
                MMA_F16(sacc[ni], qlo[ks][0], qlo[ks][1], qlo[ks][2], qlo[ks][3], kh0, kh1);
                MMA_F16(sacc[ni], qhi[ks][0], qhi[ks][1], qhi[ks][2], qhi[ks][3], kl0, kl1);
                MMA_F16(sacc[ni], qhi[ks][0], qhi[ks][1], qhi[ks][2], qhi[ks][3], kh0, kh1);
            }
        }

        // ---- online softmax (rows gr -> m0/l0, gr+8 -> m1/l1) ----
        float t0 = -INFINITY, t1 = -INFINITY;
        #pragma unroll
        for (int ni = 0; ni < 8; ni++) {
            t0 = fmaxf(t0, fmaxf(sacc[ni][0], sacc[ni][1]));
            t1 = fmaxf(t1, fmaxf(sacc[ni][2], sacc[ni][3]));
        }
        t0 = fmaxf(t0, __shfl_xor_sync(0xffffffffu, t0, 1));
        t0 = fmaxf(t0, __shfl_xor_sync(0xffffffffu, t0, 2));
        t1 = fmaxf(t1, __shfl_xor_sync(0xffffffffu, t1, 1));
        t1 = fmaxf(t1, __shfl_xor_sync(0xffffffffu, t1, 2));
        float mn0 = fmaxf(m0, t0), mn1 = fmaxf(m1, t1);
        float a0 = __expf(m0 - mn0), a1 = __expf(m1 - mn1);
        l0 *= a0; l1 *= a1;
        #pragma unroll
        for (int ni = 0; ni < 8; ni++) {
            oacc[ni][0] *= a0; oacc[ni][1] *= a0;
            oacc[ni][2] *= a1; oacc[ni][3] *= a1;
        }

        // ---- P = exp(S - m), packed as A-fragments (hi/lo) ----
        uint32_t phi[4][4], plo[4][4];
        #pragma unroll
        for (int kt = 0; kt < 4; kt++) {
            float p00 = __expf(sacc[2*kt][0]   - mn0);
            float p01 = __expf(sacc[2*kt][1]   - mn0);
            float p02 = __expf(sacc[2*kt][2]   - mn1);
            float p03 = __expf(sacc[2*kt][3]   - mn1);
            float p10 = __expf(sacc[2*kt+1][0] - mn0);
            float p11 = __expf(sacc[2*kt+1][1] - mn0);
            float p12 = __expf(sacc[2*kt+1][2] - mn1);
            float p13 = __expf(sacc[2*kt+1][3] - mn1);
            l0 += p00 + p01 + p10 + p11;
            l1 += p02 + p03 + p12 + p13;
            split2(p00, p01, phi[kt][0], plo[kt][0]);   // a0: row gr,   keys 16kt+2gc..
            split2(p02, p03, phi[kt][1], plo[kt][1]);   // a1: row gr+8
            split2(p10, p11, phi[kt][2], plo[kt][2]);   // a2: row gr,   keys +8
            split2(p12, p13, phi[kt][3], plo[kt][3]);   // a3: row gr+8
        }

        // ---- O += P V, 3xFP16 ----
        #pragma unroll
        for (int kt = 0; kt < 4; kt++) {
            #pragma unroll
            for (int nd = 0; nd < 8; nd++) {
                int bi = (nd * 8 + gr) * KSTR + kt * 8 + gc;
                uint32_t vh0 = Vhi[bi], vh1 = Vhi[bi + 4];
                uint32_t vl0 = Vlo[bi], vl1 = Vlo[bi + 4];
                MMA_F16(oacc[nd], plo[kt][0], plo[kt][1], plo[kt][2], plo[kt][3], vh0, vh1);
                MMA_F16(oacc[nd], phi[kt][0], phi[kt][1], phi[kt][2], phi[kt][3], vl0, vl1);
                MMA_F16(oacc[nd], phi[kt][0], phi[kt][1], phi[kt][2], phi[kt][3], vh0, vh1);
            }
        }
        m0 = mn0; m1 = mn1;
    }

    l0 += __shfl_xor_sync(0xffffffffu, l0, 1);
    l0 += __shfl_xor_sync(0xffffffffu, l0, 2);
    l1 += __shfl_xor_sync(0xffffffffu, l1, 1);
    l1 += __shfl_xor_sync(0xffffffffu, l1, 2);
    float i0 = 1.0f / l0, i1 = 1.0f / l1;

    #pragma unroll
    for (int nd = 0; nd < 8; nd++) {
        int col = h * DHEAD + nd * 8 + 2 * gc;
        *(float2*)(out + (size_t)(b * SEQ + q0 + gr) * INNER + col) =
            make_float2(oacc[nd][0] * i0, oacc[nd][1] * i0);
        *(float2*)(out + (size_t)(b * SEQ + q0 + 8 + gr) * INNER + col) =
            make_float2(oacc[nd][2] * i1, oacc[nd][3] * i1);
    }
}

// ===========================================================================
extern "C" void kernel_launch(void* const* d_in, const int* in_sizes, int n_in,
                              void* d_out, int out_size)
{
    const float* x     = (const float*)d_in[0];
    const float* ln_g  = (const float*)d_in[1];
    const float* q_g   = (const float*)d_in[2];
    const float* k_g   = (const float*)d_in[3];
    const float* w_qkv = (const float*)d_in[4];
    const float* w_out = (const float*)d_in[5];
    float* out = (float*)d_out;

    float *xn, *qkv, *att;
    cudaGetSymbolAddress((void**)&xn,  g_xn);
    cudaGetSymbolAddress((void**)&qkv, g_qkv);
    cudaGetSymbolAddress((void**)&att, g_att);

    ln_kernel<<<ROWS, 256>>>(x, ln_g, xn);

    gemm_f16x3<<<dim3(3 * INNER / 128, ROWS / 128), 256>>>(xn, w_qkv, qkv,
                                                           ROWS, 3 * INNER, DIM);

    rms_kernel<<<ROWS, 512>>>(qkv, q_g, k_g);

    attn_mma<<<dim3(BATCH * HEADS, SEQ / 128), 256>>>(qkv, att);

    gemm_f16x3<<<dim3(DIM / 128, ROWS / 128), 256>>>(att, w_out, out,
                                                     ROWS, DIM, INNER);
}

// round 13
// speedup vs baseline: 2.1232x; 1.0043x over previous
#include <cuda_runtime.h>
#include <cuda_fp16.h>
#include <math.h>
#include <stdint.h>

#define DIM     1024
#define HEADS   16
#define DHEAD   64
#define INNER   1024
#define SEQ     1024
#define BATCH   8
#define ROWS    (BATCH*SEQ)   // 8192

// Scratch (allocation-free rule: __device__ globals)
__device__ float g_xn [ROWS * DIM];
__device__ float g_qkv[ROWS * 3 * INNER];
__device__ float g_att[ROWS * INNER];

// ---------------------------------------------------------------------------
// helpers: fp16 hi/lo split (3xFP16 error compensation)
// ---------------------------------------------------------------------------
__device__ __forceinline__ uint32_t pack2(float x, float y) {
    __half2 h = __floats2half2_rn(x, y);
    return *reinterpret_cast<uint32_t*>(&h);
}
__device__ __forceinline__ void split2(float x, float y, uint32_t& hi, uint32_t& lo) {
    float hx = __half2float(__float2half_rn(x));
    float hy = __half2float(__float2half_rn(y));
    hi = pack2(hx, hy);
    lo = pack2(x - hx, y - hy);
}

#define MMA_F16(c, A0, A1, A2, A3, B0, B1)                                    \
    asm volatile("mma.sync.aligned.m16n8k16.row.col.f32.f16.f16.f32 "         \
                 "{%0,%1,%2,%3}, {%4,%5,%6,%7}, {%8,%9}, {%0,%1,%2,%3};"      \
                 : "+f"((c)[0]), "+f"((c)[1]), "+f"((c)[2]), "+f"((c)[3])     \
                 : "r"(A0), "r"(A1), "r"(A2), "r"(A3), "r"(B0), "r"(B1))

// ===========================================================================
// 3xFP16 mma GEMM with register double-buffering of global loads.
// C[M,N] = A[M,K]*B[K,N], row-major. 128x128x32 CTA tile, 256 thr, 64x32
// warp tile. SMEM holds pre-split hi/lo halves, row stride 40 halves.
// ===========================================================================
#define ASTR 20   // b32 per row (32 halves data + 8 pad)

__global__ __launch_bounds__(256) void gemm_f16x3(const float* __restrict__ A,
                                                  const float* __restrict__ B,
                                                  float* __restrict__ C,
                                                  int M, int N, int K)
{
    __shared__ __align__(16) uint32_t Ahi[128 * ASTR];
    __shared__ __align__(16) uint32_t Alo[128 * ASTR];
    __shared__ __align__(16) uint32_t Bhi[128 * ASTR];
    __shared__ __align__(16) uint32_t Blo[128 * ASTR];

    const int tid  = threadIdx.x;
    const int lane = tid & 31;
    const int wid  = tid >> 5;
    const int mw   = wid >> 2;
    const int nw   = wid & 3;
    const int brow = blockIdx.y * 128;
    const int bcol = blockIdx.x * 128;
    const int gr   = lane >> 2;
    const int gc   = lane & 3;

    float acc[4][4][4];
    #pragma unroll
    for (int i = 0; i < 4; i++)
        #pragma unroll
        for (int j = 0; j < 4; j++)
            #pragma unroll
            for (int c = 0; c < 4; c++) acc[i][j][c] = 0.f;

    const int a_row = tid >> 3;          // 0..31 base row step 32
    const int a_c4  = tid & 7;
    const int b_k   = tid & 31;
    const int b_ng  = tid >> 5;

    // ---- prologue: load tile 0 into registers ----
    float4 aR[4], bR[4];
    #pragma unroll
    for (int j = 0; j < 4; j++) {
        aR[j] = *(const float4*)(A + (size_t)(brow + a_row + j * 32) * K + a_c4 * 4);
        bR[j] = *(const float4*)(B + (size_t)b_k * N + bcol + (b_ng + j * 8) * 4);
    }

    for (int k0 = 0; k0 < K; k0 += 32) {
        // ---- STS current tile from registers (convert + split) ----
        #pragma unroll
        for (int j = 0; j < 4; j++) {
            uint32_t h0, l0, h1, l1;
            split2(aR[j].x, aR[j].y, h0, l0);
            split2(aR[j].z, aR[j].w, h1, l1);
            int idx = (a_row + j * 32) * ASTR + a_c4 * 2;
            *(uint2*)&Ahi[idx] = make_uint2(h0, h1);
            *(uint2*)&Alo[idx] = make_uint2(l0, l1);

            int n4 = b_ng + j * 8;
            float vv[4] = {bR[j].x, bR[j].y, bR[j].z, bR[j].w};
            #pragma unroll
            for (int c = 0; c < 4; c++) {
                __half hh = __float2half_rn(vv[c]);
                __half hl = __float2half_rn(vv[c] - __half2float(hh));
                int hidx = (n4 * 4 + c) * (ASTR * 2) + b_k;
                reinterpret_cast<__half*>(Bhi)[hidx] = hh;
                reinterpret_cast<__half*>(Blo)[hidx] = hl;
            }
        }
        __syncthreads();

        // ---- prefetch next tile (overlaps with compute below) ----
        if (k0 + 32 < K) {
            #pragma unroll
            for (int j = 0; j < 4; j++) {
                aR[j] = *(const float4*)(A + (size_t)(brow + a_row + j * 32) * K
                                         + (k0 + 32) + a_c4 * 4);
                bR[j] = *(const float4*)(B + (size_t)(k0 + 32 + b_k) * N
                                         + bcol + (b_ng + j * 8) * 4);
            }
        }

        // ---- compute ----
        #pragma unroll
        for (int ks = 0; ks < 2; ks++) {
            uint32_t bh[4][2], bl[4][2];
            #pragma unroll
            for (int ni = 0; ni < 4; ni++) {
                int n  = nw * 32 + ni * 8 + gr;
                int bi = n * ASTR + ks * 8 + gc;
                bh[ni][0] = Bhi[bi]; bh[ni][1] = Bhi[bi + 4];
                bl[ni][0] = Blo[bi]; bl[ni][1] = Blo[bi + 4];
            }
            #pragma unroll
            for (int mi = 0; mi < 4; mi++) {
                int r   = mw * 64 + mi * 16 + gr;
                int ai  = r * ASTR + ks * 8 + gc;
                int ai8 = ai + 8 * ASTR;
                uint32_t ah0 = Ahi[ai],  ah1 = Ahi[ai8];
                uint32_t ah2 = Ahi[ai + 4], ah3 = Ahi[ai8 + 4];
                uint32_t al0 = Alo[ai],  al1 = Alo[ai8];
                uint32_t al2 = Alo[ai + 4], al3 = Alo[ai8 + 4];
                #pragma unroll
                for (int ni = 0; ni < 4; ni++) {
                    MMA_F16(acc[mi][ni], al0, al1, al2, al3, bh[ni][0], bh[ni][1]);
                    MMA_F16(acc[mi][ni], ah0, ah1, ah2, ah3, bl[ni][0], bl[ni][1]);
                    MMA_F16(acc[mi][ni], ah0, ah1, ah2, ah3, bh[ni][0], bh[ni][1]);
                }
            }
        }
        __syncthreads();
    }

    #pragma unroll
    for (int mi = 0; mi < 4; mi++) {
        int row = brow + mw * 64 + mi * 16 + gr;
        #pragma unroll
        for (int ni = 0; ni < 4; ni++) {
            int col = bcol + nw * 32 + ni * 8 + gc * 2;
            *(float2*)(C + (size_t)row * N + col) =
                make_float2(acc[mi][ni][0], acc[mi][ni][1]);
            *(float2*)(C + (size_t)(row + 8) * N + col) =
                make_float2(acc[mi][ni][2], acc[mi][ni][3]);
        }
    }
}

// ===========================================================================
// LayerNorm
// ===========================================================================
__global__ __launch_bounds__(256) void ln_kernel(const float* __restrict__ x,
                                                 const float* __restrict__ gamma,
                                                 float* __restrict__ out)
{
    int row = blockIdx.x;
    const float4* xr = (const float4*)(x + (size_t)row * DIM);
    float4 v = xr[threadIdx.x];
    float s  = v.x + v.y + v.z + v.w;
    float ss = v.x*v.x + v.y*v.y + v.z*v.z + v.w*v.w;
    #pragma unroll
    for (int o = 16; o > 0; o >>= 1) {
        s  += __shfl_down_sync(0xffffffffu, s,  o);
        ss += __shfl_down_sync(0xffffffffu, ss, o);
    }
    __shared__ float sh_s[8], sh_ss[8];
    int w = threadIdx.x >> 5, lane = threadIdx.x & 31;
    if (lane == 0) { sh_s[w] = s; sh_ss[w] = ss; }
    __syncthreads();
    if (w == 0) {
        s  = (lane < 8) ? sh_s[lane]  : 0.f;
        ss = (lane < 8) ? sh_ss[lane] : 0.f;
        #pragma unroll
        for (int o = 4; o > 0; o >>= 1) {
            s  += __shfl_down_sync(0xffffffffu, s,  o);
            ss += __shfl_down_sync(0xffffffffu, ss, o);
        }
        if (lane == 0) { sh_s[0] = s; sh_ss[0] = ss; }
    }
    __syncthreads();
    float mu  = sh_s[0]  * (1.0f / DIM);
    float var = sh_ss[0] * (1.0f / DIM) - mu * mu;
    float inv = rsqrtf(var + 1e-5f);
    float4 g = ((const float4*)gamma)[threadIdx.x];
    float4 r;
    r.x = (v.x - mu) * inv * g.x;
    r.y = (v.y - mu) * inv * g.y;
    r.z = (v.z - mu) * inv * g.z;
    r.w = (v.w - mu) * inv * g.w;
    ((float4*)(out + (size_t)row * DIM))[threadIdx.x] = r;
}

// ===========================================================================
// Per-head RMS on q,k in place
// ===========================================================================
__global__ __launch_bounds__(512) void rms_kernel(float* __restrict__ qkv,
                                                  const float* __restrict__ qg,
                                                  const float* __restrict__ kg)
{
    int row    = blockIdx.x;
    int unit   = threadIdx.x >> 4;
    int lane16 = threadIdx.x & 15;
    int qk     = unit >> 4;
    int head   = unit & 15;

    float* p = qkv + (size_t)row * (3 * INNER) + qk * INNER + head * DHEAD;
    float4 v = ((float4*)p)[lane16];
    float ss = v.x*v.x + v.y*v.y + v.z*v.z + v.w*v.w;
    #pragma unroll
    for (int o = 8; o > 0; o >>= 1)
        ss += __shfl_xor_sync(0xffffffffu, ss, o, 16);
    float n = sqrtf(ss);
    float scale = 8.0f / fmaxf(n, 1e-12f);

    const float* g = (qk ? kg : qg) + head * DHEAD + lane16 * 4;
    v.x *= scale * g[0];
    v.y *= scale * g[1];
    v.z *= scale * g[2];
    v.w *= scale * g[3];
    ((float4*)p)[lane16] = v;
}

// ===========================================================================
// MMA flash attention (FA-2) with register double-buffered K/V tiles.
// 256 thr, 8 warps x 16 q-rows = 128 q / CTA. 64-key tiles, 3xFP16 mma.
// ===========================================================================
#define KSTR 36   // b32 per row (64 halves data + 8 pad)

__global__ __launch_bounds__(256) void attn_mma(const float* __restrict__ qkv,
                                                float* __restrict__ out)
{
    __shared__ __align__(16) uint32_t Khi[64 * KSTR];
    __shared__ __align__(16) uint32_t Klo[64 * KSTR];
    __shared__ __align__(16) uint32_t Vhi[64 * KSTR];
    __shared__ __align__(16) uint32_t Vlo[64 * KSTR];

    const int tid  = threadIdx.x;
    const int lane = tid & 31;
    const int wid  = tid >> 5;
    const int gr   = lane >> 2;
    const int gc   = lane & 3;

    const int bh = blockIdx.x;
    const int b  = bh >> 4, h = bh & 15;
    const int q0 = blockIdx.y * 128 + wid * 16;
    const size_t base = (size_t)b * SEQ * (3 * INNER);
    const float* qp = qkv + base + h * DHEAD;

    // ---- Q fragments (hi/lo), kept in registers ----
    uint32_t qhi[4][4], qlo[4][4];
    #pragma unroll
    for (int ks = 0; ks < 4; ks++) {
        int r0 = q0 + gr, r1 = q0 + 8 + gr;
        int d0 = ks * 16 + 2 * gc, d1 = d0 + 8;
        float2 x00 = *(const float2*)(qp + (size_t)r0 * (3 * INNER) + d0);
        float2 x10 = *(const float2*)(qp + (size_t)r1 * (3 * INNER) + d0);
        float2 x01 = *(const float2*)(qp + (size_t)r0 * (3 * INNER) + d1);
        float2 x11 = *(const float2*)(qp + (size_t)r1 * (3 * INNER) + d1);
        split2(x00.x, x00.y, qhi[ks][0], qlo[ks][0]);
        split2(x10.x, x10.y, qhi[ks][1], qlo[ks][1]);
        split2(x01.x, x01.y, qhi[ks][2], qlo[ks][2]);
        split2(x11.x, x11.y, qhi[ks][3], qlo[ks][3]);
    }

    float oacc[8][4];
    #pragma unroll
    for (int i = 0; i < 8; i++)
        #pragma unroll
        for (int c = 0; c < 4; c++) oacc[i][c] = 0.f;
    float m0 = -INFINITY, m1 = -INFINITY, l0 = 0.f, l1 = 0.f;

    const int f_key = tid >> 4;          // 0..15 (base key, step 16)
    const int f_d4  = tid & 15;
    const float* kbase = qkv + base + INNER + h * DHEAD + f_d4 * 4;

    // ---- prologue: load K/V tile 0 into registers ----
    float4 kR[4], vR[4];
    #pragma unroll
    for (int j = 0; j < 4; j++) {
        const float* kp = kbase + (size_t)(f_key + j * 16) * (3 * INNER);
        kR[j] = *(const float4*)kp;
        vR[j] = *(const float4*)(kp + INNER);
    }

    for (int n0 = 0; n0 < SEQ; n0 += 64) {
        // ---- STS tile from registers ----
        #pragma unroll
        for (int j = 0; j < 4; j++) {
            int key = f_key + j * 16;
            uint32_t h0, l0u, h1, l1u;
            split2(kR[j].x, kR[j].y, h0, l0u);
            split2(kR[j].z, kR[j].w, h1, l1u);
            int idx = key * KSTR + f_d4 * 2;
            *(uint2*)&Khi[idx] = make_uint2(h0, h1);
            *(uint2*)&Klo[idx] = make_uint2(l0u, l1u);

            float va[4] = {vR[j].x, vR[j].y, vR[j].z, vR[j].w};
            #pragma unroll
            for (int c = 0; c < 4; c++) {
                int d = f_d4 * 4 + c;
                __half hh = __float2half_rn(va[c]);
                int hidx = d * (KSTR * 2) + key;
                reinterpret_cast<__half*>(Vhi)[hidx] = hh;
                reinterpret_cast<__half*>(Vlo)[hidx] =
                    __float2half_rn(va[c] - __half2float(hh));
            }
        }
        __syncthreads();

        // ---- prefetch next K/V tile ----
        if (n0 + 64 < SEQ) {
            #pragma unroll
            for (int j = 0; j < 4; j++) {
                const float* kp = kbase + (size_t)(n0 + 64 + f_key + j * 16) * (3 * INNER);
                kR[j] = *(const float4*)kp;
                vR[j] = *(const float4*)(kp + INNER);
            }
        }

        // ---- S = Q K^T ----
        float sacc[8][4];
        #pragma unroll
        for (int i = 0; i < 8; i++)
            #pragma unroll
            for (int c = 0; c < 4; c++) sacc[i][c] = 0.f;

        #pragma unroll
        for (int ks = 0; ks < 4; ks++) {
            #pragma unroll
            for (int ni = 0; ni < 8; ni++) {
                int bi = (ni * 8 + gr) * KSTR + ks * 8 + gc;
                uint32_t kh0 = Khi[bi], kh1 = Khi[bi + 4];
                uint32_t kl0 = Klo[bi], kl1 = Klo[bi + 4];
                MMA_F16(sacc[ni], qlo[ks][0], qlo[ks][1], qlo[ks][2], qlo[ks][3], kh0, kh1);
                MMA_F16(sacc[ni], qhi[ks][0], qhi[ks][1], qhi[ks][2], qhi[ks][3], kl0, kl1);
                MMA_F16(sacc[ni], qhi[ks][0], qhi[ks][1], qhi[ks][2], qhi[ks][3], kh0, kh1);
            }
        }

        // ---- online softmax ----
        float t0 = -INFINITY, t1 = -INFINITY;
        #pragma unroll
        for (int ni = 0; ni < 8; ni++) {
            t0 = fmaxf(t0, fmaxf(sacc[ni][0], sacc[ni][1]));
            t1 = fmaxf(t1, fmaxf(sacc[ni][2], sacc[ni][3]));
        }
        t0 = fmaxf(t0, __shfl_xor_sync(0xffffffffu, t0, 1));
        t0 = fmaxf(t0, __shfl_xor_sync(0xffffffffu, t0, 2));
        t1 = fmaxf(t1, __shfl_xor_sync(0xffffffffu, t1, 1));
        t1 = fmaxf(t1, __shfl_xor_sync(0xffffffffu, t1, 2));
        float mn0 = fmaxf(m0, t0), mn1 = fmaxf(m1, t1);
        float a0 = __expf(m0 - mn0), a1 = __expf(m1 - mn1);
        l0 *= a0; l1 *= a1;
        #pragma unroll
        for (int ni = 0; ni < 8; ni++) {
            oacc[ni][0] *= a0; oacc[ni][1] *= a0;
            oacc[ni][2] *= a1; oacc[ni][3] *= a1;
        }

        // ---- P = exp(S - m), as A-fragments ----
        uint32_t phi[4][4], plo[4][4];
        #pragma unroll
        for (int kt = 0; kt < 4; kt++) {
            float p00 = __expf(sacc[2*kt][0]   - mn0);
            float p01 = __expf(sacc[2*kt][1]   - mn0);
            float p02 = __expf(sacc[2*kt][2]   - mn1);
            float p03 = __expf(sacc[2*kt][3]   - mn1);
            float p10 = __expf(sacc[2*kt+1][0] - mn0);
            float p11 = __expf(sacc[2*kt+1][1] - mn0);
            float p12 = __expf(sacc[2*kt+1][2] - mn1);
            float p13 = __expf(sacc[2*kt+1][3] - mn1);
            l0 += p00 + p01 + p10 + p11;
            l1 += p02 + p03 + p12 + p13;
            split2(p00, p01, phi[kt][0], plo[kt][0]);
            split2(p02, p03, phi[kt][1], plo[kt][1]);
            split2(p10, p11, phi[kt][2], plo[kt][2]);
            split2(p12, p13, phi[kt][3], plo[kt][3]);
        }

        // ---- O += P V ----
        #pragma unroll
        for (int kt = 0; kt < 4; kt++) {
            #pragma unroll
            for (int nd = 0; nd < 8; nd++) {
                int bi = (nd * 8 + gr) * KSTR + kt * 8 + gc;
                uint32_t vh0 = Vhi[bi], vh1 = Vhi[bi + 4];
                uint32_t vl0 = Vlo[bi], vl1 = Vlo[bi + 4];
                MMA_F16(oacc[nd], plo[kt][0], plo[kt][1], plo[kt][2], plo[kt][3], vh0, vh1);
                MMA_F16(oacc[nd], phi[kt][0], phi[kt][1], phi[kt][2], phi[kt][3], vl0, vl1);
                MMA_F16(oacc[nd], phi[kt][0], phi[kt][1], phi[kt][2], phi[kt][3], vh0, vh1);
            }
        }
        m0 = mn0; m1 = mn1;
        __syncthreads();
    }

    l0 += __shfl_xor_sync(0xffffffffu, l0, 1);
    l0 += __shfl_xor_sync(0xffffffffu, l0, 2);
    l1 += __shfl_xor_sync(0xffffffffu, l1, 1);
    l1 += __shfl_xor_sync(0xffffffffu, l1, 2);
    float i0 = 1.0f / l0, i1 = 1.0f / l1;

    #pragma unroll
    for (int nd = 0; nd < 8; nd++) {
        int col = h * DHEAD + nd * 8 + 2 * gc;
        *(float2*)(out + (size_t)(b * SEQ + q0 + gr) * INNER + col) =
            make_float2(oacc[nd][0] * i0, oacc[nd][1] * i0);
        *(float2*)(out + (size_t)(b * SEQ + q0 + 8 + gr) * INNER + col) =
            make_float2(oacc[nd][2] * i1, oacc[nd][3] * i1);
    }
}

// ===========================================================================
extern "C" void kernel_launch(void* const* d_in, const int* in_sizes, int n_in,
                              void* d_out, int out_size)
{
    const float* x     = (const float*)d_in[0];
    const float* ln_g  = (const float*)d_in[1];
    const float* q_g   = (const float*)d_in[2];
    const float* k_g   = (const float*)d_in[3];
    const float* w_qkv = (const float*)d_in[4];
    const float* w_out = (const float*)d_in[5];
    float* out = (float*)d_out;

    float *xn, *qkv, *att;
    cudaGetSymbolAddress((void**)&xn,  g_xn);
    cudaGetSymbolAddress((void**)&qkv, g_qkv);
    cudaGetSymbolAddress((void**)&att, g_att);

    ln_kernel<<<ROWS, 256>>>(x, ln_g, xn);

    gemm_f16x3<<<dim3(3 * INNER / 128, ROWS / 128), 256>>>(xn, w_qkv, qkv,
                                                           ROWS, 3 * INNER, DIM);

    rms_kernel<<<ROWS, 512>>>(qkv, q_g, k_g);

    attn_mma<<<dim3(BATCH * HEADS, SEQ / 128), 256>>>(qkv, att);

    gemm_f16x3<<<dim3(DIM / 128, ROWS / 128), 256>>>(att, w_out, out,
                                                     ROWS, DIM, INNER);
}

// round 14
// speedup vs baseline: 2.3652x; 1.1140x over previous
#include <cuda_runtime.h>
#include <cuda_fp16.h>
#include <math.h>
#include <stdint.h>

#define DIM     1024
#define HEADS   16
#define DHEAD   64
#define INNER   1024
#define SEQ     1024
#define BATCH   8
#define ROWS    (BATCH*SEQ)   // 8192

// Scratch (allocation-free rule: __device__ globals)
__device__ float g_xn [ROWS * DIM];
__device__ float g_qkv[ROWS * 3 * INNER];
__device__ float g_att[ROWS * INNER];

// ---------------------------------------------------------------------------
// helpers
// ---------------------------------------------------------------------------
__device__ __forceinline__ uint32_t pack2(float x, float y) {
    __half2 h = __floats2half2_rn(x, y);
    return *reinterpret_cast<uint32_t*>(&h);
}
__device__ __forceinline__ void split2(float x, float y, uint32_t& hi, uint32_t& lo) {
    float hx = __half2float(__float2half_rn(x));
    float hy = __half2float(__float2half_rn(y));
    hi = pack2(hx, hy);
    lo = pack2(x - hx, y - hy);
}
__device__ __forceinline__ uint32_t cvta_s(const void* p) {
    uint32_t a;
    asm("{ .reg .u64 t; cvta.to.shared.u64 t, %1; cvt.u32.u64 %0, t; }" : "=r"(a) : "l"(p));
    return a;
}

#define MMA_F16(c, A0, A1, A2, A3, B0, B1)                                    \
    asm volatile("mma.sync.aligned.m16n8k16.row.col.f32.f16.f16.f32 "         \
                 "{%0,%1,%2,%3}, {%4,%5,%6,%7}, {%8,%9}, {%0,%1,%2,%3};"      \
                 : "+f"((c)[0]), "+f"((c)[1]), "+f"((c)[2]), "+f"((c)[3])     \
                 : "r"(A0), "r"(A1), "r"(A2), "r"(A3), "r"(B0), "r"(B1))

#define LDSM4(r0, r1, r2, r3, a)                                              \
    asm volatile("ldmatrix.sync.aligned.m8n8.x4.shared.b16 {%0,%1,%2,%3}, [%4];" \
                 : "=r"(r0), "=r"(r1), "=r"(r2), "=r"(r3) : "r"(a))

// ===========================================================================
// 3xFP16 mma GEMM (ldmatrix fragments): C[M,N] = A[M,K]*B[K,N], row-major.
// 128x128x32 CTA tile, 256 thr, 64x32 warp tile, 2 CTAs/SM.
// SMEM: pre-split hi/lo halves; A rows [m][k], B rows [n][k]; stride 20 b32.
// ===========================================================================
#define ASTR 20   // b32 per row (32 halves data + 8 pad) -> 80 bytes

__global__ __launch_bounds__(256, 2) void gemm_f16x3(const float* __restrict__ A,
                                                     const float* __restrict__ B,
                                                     float* __restrict__ C,
                                                     int M, int N, int K)
{
    __shared__ __align__(16) uint32_t Ahi[128 * ASTR];
    __shared__ __align__(16) uint32_t Alo[128 * ASTR];
    __shared__ __align__(16) uint32_t Bhi[128 * ASTR];
    __shared__ __align__(16) uint32_t Blo[128 * ASTR];

    const int tid  = threadIdx.x;
    const int lane = tid & 31;
    const int wid  = tid >> 5;
    const int mw   = wid >> 2;
    const int nw   = wid & 3;
    const int brow = blockIdx.y * 128;
    const int bcol = blockIdx.x * 128;
    const int gr   = lane >> 2;
    const int gc   = lane & 3;

    const uint32_t AhiB = cvta_s(Ahi), AloB = cvta_s(Alo);
    const uint32_t BhiB = cvta_s(Bhi), BloB = cvta_s(Blo);

    // ldmatrix lane addressing components
    const int lm_row  = (lane & 15);                 // A: row offset
    const int lm_kofA = (lane >> 4) << 3;            // A: +8 khalf for upper 16 lanes
    const int lm_rowB = (lane & 7) + ((lane >> 4) << 3);  // B: n offset
    const int lm_kofB = ((lane >> 3) & 1) << 3;      // B: +8 khalf

    float acc[4][4][4];
    #pragma unroll
    for (int i = 0; i < 4; i++)
        #pragma unroll
        for (int j = 0; j < 4; j++)
            #pragma unroll
            for (int c = 0; c < 4; c++) acc[i][j][c] = 0.f;

    const int a_row = tid >> 3;
    const int a_c4  = tid & 7;
    const int b_k   = tid & 31;
    const int b_ng  = tid >> 5;

    for (int k0 = 0; k0 < K; k0 += 32) {
        // ---- A fill: 128x32, split once ----
        #pragma unroll
        for (int j = 0; j < 4; j++) {
            int row = a_row + j * 32;
            float4 v = *(const float4*)(A + (size_t)(brow + row) * K + k0 + a_c4 * 4);
            uint32_t h0, l0, h1, l1;
            split2(v.x, v.y, h0, l0);
            split2(v.z, v.w, h1, l1);
            int idx = row * ASTR + a_c4 * 2;
            *(uint2*)&Ahi[idx] = make_uint2(h0, h1);
            *(uint2*)&Alo[idx] = make_uint2(l0, l1);
        }
        // ---- B fill: 32x128 -> Bs[n][k] transposed halves ----
        #pragma unroll
        for (int j = 0; j < 4; j++) {
            int n4 = b_ng + j * 8;
            float4 v = *(const float4*)(B + (size_t)(k0 + b_k) * N + bcol + n4 * 4);
            float vv[4] = {v.x, v.y, v.z, v.w};
            #pragma unroll
            for (int c = 0; c < 4; c++) {
                __half hh = __float2half_rn(vv[c]);
                __half hl = __float2half_rn(vv[c] - __half2float(hh));
                int hidx = (n4 * 4 + c) * (ASTR * 2) + b_k;
                reinterpret_cast<__half*>(Bhi)[hidx] = hh;
                reinterpret_cast<__half*>(Blo)[hidx] = hl;
            }
        }
        __syncthreads();

        #pragma unroll
        for (int ks = 0; ks < 2; ks++) {
            // ---- B fragments via ldmatrix.x4 (2 ni per load) ----
            uint32_t bh[4][2], bl[4][2];
            #pragma unroll
            for (int np = 0; np < 2; np++) {
                int n  = nw * 32 + np * 16 + lm_rowB;
                uint32_t off = (uint32_t)(n * 80 + (ks * 16 + lm_kofB) * 2);
                LDSM4(bh[2*np][0], bh[2*np][1], bh[2*np+1][0], bh[2*np+1][1], BhiB + off);
                LDSM4(bl[2*np][0], bl[2*np][1], bl[2*np+1][0], bl[2*np+1][1], BloB + off);
            }
            #pragma unroll
            for (int mi = 0; mi < 4; mi++) {
                int r = mw * 64 + mi * 16 + lm_row;
                uint32_t off = (uint32_t)(r * 80 + (ks * 16 + lm_kofA) * 2);
                uint32_t ah0, ah1, ah2, ah3, al0, al1, al2, al3;
                LDSM4(ah0, ah1, ah2, ah3, AhiB + off);
                LDSM4(al0, al1, al2, al3, AloB + off);
                #pragma unroll
                for (int ni = 0; ni < 4; ni++) {
                    MMA_F16(acc[mi][ni], al0, al1, al2, al3, bh[ni][0], bh[ni][1]);
                    MMA_F16(acc[mi][ni], ah0, ah1, ah2, ah3, bl[ni][0], bl[ni][1]);
                    MMA_F16(acc[mi][ni], ah0, ah1, ah2, ah3, bh[ni][0], bh[ni][1]);
                }
            }
        }
        __syncthreads();
    }

    #pragma unroll
    for (int mi = 0; mi < 4; mi++) {
        int row = brow + mw * 64 + mi * 16 + gr;
        #pragma unroll
        for (int ni = 0; ni < 4; ni++) {
            int col = bcol + nw * 32 + ni * 8 + gc * 2;
            *(float2*)(C + (size_t)row * N + col) =
                make_float2(acc[mi][ni][0], acc[mi][ni][1]);
            *(float2*)(C + (size_t)(row + 8) * N + col) =
                make_float2(acc[mi][ni][2], acc[mi][ni][3]);
        }
    }
}

// ===========================================================================
// LayerNorm
// ===========================================================================
__global__ __launch_bounds__(256) void ln_kernel(const float* __restrict__ x,
                                                 const float* __restrict__ gamma,
                                                 float* __restrict__ out)
{
    int row = blockIdx.x;
    const float4* xr = (const float4*)(x + (size_t)row * DIM);
    float4 v = xr[threadIdx.x];
    float s  = v.x + v.y + v.z + v.w;
    float ss = v.x*v.x + v.y*v.y + v.z*v.z + v.w*v.w;
    #pragma unroll
    for (int o = 16; o > 0; o >>= 1) {
        s  += __shfl_down_sync(0xffffffffu, s,  o);
        ss += __shfl_down_sync(0xffffffffu, ss, o);
    }
    __shared__ float sh_s[8], sh_ss[8];
    int w = threadIdx.x >> 5, lane = threadIdx.x & 31;
    if (lane == 0) { sh_s[w] = s; sh_ss[w] = ss; }
    __syncthreads();
    if (w == 0) {
        s  = (lane < 8) ? sh_s[lane]  : 0.f;
        ss = (lane < 8) ? sh_ss[lane] : 0.f;
        #pragma unroll
        for (int o = 4; o > 0; o >>= 1) {
            s  += __shfl_down_sync(0xffffffffu, s,  o);
            ss += __shfl_down_sync(0xffffffffu, ss, o);
        }
        if (lane == 0) { sh_s[0] = s; sh_ss[0] = ss; }
    }
    __syncthreads();
    float mu  = sh_s[0]  * (1.0f / DIM);
    float var = sh_ss[0] * (1.0f / DIM) - mu * mu;
    float inv = rsqrtf(var + 1e-5f);
    float4 g = ((const float4*)gamma)[threadIdx.x];
    float4 r;
    r.x = (v.x - mu) * inv * g.x;
    r.y = (v.y - mu) * inv * g.y;
    r.z = (v.z - mu) * inv * g.z;
    r.w = (v.w - mu) * inv * g.w;
    ((float4*)(out + (size_t)row * DIM))[threadIdx.x] = r;
}

// ===========================================================================
// Per-head RMS on q,k in place
// ===========================================================================
__global__ __launch_bounds__(512) void rms_kernel(float* __restrict__ qkv,
                                                  const float* __restrict__ qg,
                                                  const float* __restrict__ kg)
{
    int row    = blockIdx.x;
    int unit   = threadIdx.x >> 4;
    int lane16 = threadIdx.x & 15;
    int qk     = unit >> 4;
    int head   = unit & 15;

    float* p = qkv + (size_t)row * (3 * INNER) + qk * INNER + head * DHEAD;
    float4 v = ((float4*)p)[lane16];
    float ss = v.x*v.x + v.y*v.y + v.z*v.z + v.w*v.w;
    #pragma unroll
    for (int o = 8; o > 0; o >>= 1)
        ss += __shfl_xor_sync(0xffffffffu, ss, o, 16);
    float n = sqrtf(ss);
    float scale = 8.0f / fmaxf(n, 1e-12f);

    const float* g = (qk ? kg : qg) + head * DHEAD + lane16 * 4;
    v.x *= scale * g[0];
    v.y *= scale * g[1];
    v.z *= scale * g[2];
    v.w *= scale * g[3];
    ((float4*)p)[lane16] = v;
}

// ===========================================================================
// MMA flash attention (FA-2): register-prefetched K/V + ldmatrix fragments.
// 256 thr, 8 warps x 16 q-rows. 64-key tiles, 3xFP16 mma.
// K rows [key][d], V rows [d][key], stride 36 b32 = 144 bytes.
// ===========================================================================
#define KSTR 36

__global__ __launch_bounds__(256) void attn_mma(const float* __restrict__ qkv,
                                                float* __restrict__ out)
{
    __shared__ __align__(16) uint32_t Khi[64 * KSTR];
    __shared__ __align__(16) uint32_t Klo[64 * KSTR];
    __shared__ __align__(16) uint32_t Vhi[64 * KSTR];
    __shared__ __align__(16) uint32_t Vlo[64 * KSTR];

    const int tid  = threadIdx.x;
    const int lane = tid & 31;
    const int wid  = tid >> 5;
    const int gr   = lane >> 2;
    const int gc   = lane & 3;

    const uint32_t KhiB = cvta_s(Khi), KloB = cvta_s(Klo);
    const uint32_t VhiB = cvta_s(Vhi), VloB = cvta_s(Vlo);
    const int lm_rowB = (lane & 7) + ((lane >> 4) << 3);
    const int lm_kofB = ((lane >> 3) & 1) << 3;

    const int bh = blockIdx.x;
    const int b  = bh >> 4, h = bh & 15;
    const int q0 = blockIdx.y * 128 + wid * 16;
    const size_t base = (size_t)b * SEQ * (3 * INNER);
    const float* qp = qkv + base + h * DHEAD;

    // ---- Q fragments (hi/lo), kept in registers ----
    uint32_t qhi[4][4], qlo[4][4];
    #pragma unroll
    for (int ks = 0; ks < 4; ks++) {
        int r0 = q0 + gr, r1 = q0 + 8 + gr;
        int d0 = ks * 16 + 2 * gc, d1 = d0 + 8;
        float2 x00 = *(const float2*)(qp + (size_t)r0 * (3 * INNER) + d0);
        float2 x10 = *(const float2*)(qp + (size_t)r1 * (3 * INNER) + d0);
        float2 x01 = *(const float2*)(qp + (size_t)r0 * (3 * INNER) + d1);
        float2 x11 = *(const float2*)(qp + (size_t)r1 * (3 * INNER) + d1);
        split2(x00.x, x00.y, qhi[ks][0], qlo[ks][0]);
        split2(x10.x, x10.y, qhi[ks][1], qlo[ks][1]);
        split2(x01.x, x01.y, qhi[ks][2], qlo[ks][2]);
        split2(x11.x, x11.y, qhi[ks][3], qlo[ks][3]);
    }

    float oacc[8][4];
    #pragma unroll
    for (int i = 0; i < 8; i++)
        #pragma unroll
        for (int c = 0; c < 4; c++) oacc[i][c] = 0.f;
    float m0 = -INFINITY, m1 = -INFINITY, l0 = 0.f, l1 = 0.f;

    const int f_key = tid >> 4;
    const int f_d4  = tid & 15;
    const float* kbase = qkv + base + INNER + h * DHEAD + f_d4 * 4;

    // ---- prologue: load K/V tile 0 into registers ----
    float4 kR[4], vR[4];
    #pragma unroll
    for (int j = 0; j < 4; j++) {
        const float* kp = kbase + (size_t)(f_key + j * 16) * (3 * INNER);
        kR[j] = *(const float4*)kp;
        vR[j] = *(const float4*)(kp + INNER);
    }

    for (int n0 = 0; n0 < SEQ; n0 += 64) {
        // ---- STS tile from registers ----
        #pragma unroll
        for (int j = 0; j < 4; j++) {
            int key = f_key + j * 16;
            uint32_t h0, l0u, h1, l1u;
            split2(kR[j].x, kR[j].y, h0, l0u);
            split2(kR[j].z, kR[j].w, h1, l1u);
            int idx = key * KSTR + f_d4 * 2;
            *(uint2*)&Khi[idx] = make_uint2(h0, h1);
            *(uint2*)&Klo[idx] = make_uint2(l0u, l1u);

            float va[4] = {vR[j].x, vR[j].y, vR[j].z, vR[j].w};
            #pragma unroll
            for (int c = 0; c < 4; c++) {
                int d = f_d4 * 4 + c;
                __half hh = __float2half_rn(va[c]);
                int hidx = d * (KSTR * 2) + key;
                reinterpret_cast<__half*>(Vhi)[hidx] = hh;
                reinterpret_cast<__half*>(Vlo)[hidx] =
                    __float2half_rn(va[c] - __half2float(hh));
            }
        }
        __syncthreads();

        // ---- prefetch next K/V tile ----
        if (n0 + 64 < SEQ) {
            #pragma unroll
            for (int j = 0; j < 4; j++) {
                const float* kp = kbase + (size_t)(n0 + 64 + f_key + j * 16) * (3 * INNER);
                kR[j] = *(const float4*)kp;
                vR[j] = *(const float4*)(kp + INNER);
            }
        }

        // ---- S = Q K^T via ldmatrix fragments ----
        float sacc[8][4];
        #pragma unroll
        for (int i = 0; i < 8; i++)
            #pragma unroll
            for (int c = 0; c < 4; c++) sacc[i][c] = 0.f;

        #pragma unroll
        for (int ks = 0; ks < 4; ks++) {
            #pragma unroll
            for (int np = 0; np < 4; np++) {
                int n = np * 16 + lm_rowB;
                uint32_t off = (uint32_t)(n * 144 + (ks * 16 + lm_kofB) * 2);
                uint32_t kh0, kh1, kh2, kh3, kl0, kl1, kl2, kl3;
                LDSM4(kh0, kh1, kh2, kh3, KhiB + off);
                LDSM4(kl0, kl1, kl2, kl3, KloB + off);
                MMA_F16(sacc[2*np],   qlo[ks][0], qlo[ks][1], qlo[ks][2], qlo[ks][3], kh0, kh1);
                MMA_F16(sacc[2*np],   qhi[ks][0], qhi[ks][1], qhi[ks][2], qhi[ks][3], kl0, kl1);
                MMA_F16(sacc[2*np],   qhi[ks][0], qhi[ks][1], qhi[ks][2], qhi[ks][3], kh0, kh1);
                MMA_F16(sacc[2*np+1], qlo[ks][0], qlo[ks][1], qlo[ks][2], qlo[ks][3], kh2, kh3);
                MMA_F16(sacc[2*np+1], qhi[ks][0], qhi[ks][1], qhi[ks][2], qhi[ks][3], kl2, kl3);
                MMA_F16(sacc[2*np+1], qhi[ks][0], qhi[ks][1], qhi[ks][2], qhi[ks][3], kh2, kh3);
            }
        }

        // ---- online softmax ----
        float t0 = -INFINITY, t1 = -INFINITY;
        #pragma unroll
        for (int ni = 0; ni < 8; ni++) {
            t0 = fmaxf(t0, fmaxf(sacc[ni][0], sacc[ni][1]));
            t1 = fmaxf(t1, fmaxf(sacc[ni][2], sacc[ni][3]));
        }
        t0 = fmaxf(t0, __shfl_xor_sync(0xffffffffu, t0, 1));
        t0 = fmaxf(t0, __shfl_xor_sync(0xffffffffu, t0, 2));
        t1 = fmaxf(t1, __shfl_xor_sync(0xffffffffu, t1, 1));
        t1 = fmaxf(t1, __shfl_xor_sync(0xffffffffu, t1, 2));
        float mn0 = fmaxf(m0, t0), mn1 = fmaxf(m1, t1);
        float a0 = __expf(m0 - mn0), a1 = __expf(m1 - mn1);
        l0 *= a0; l1 *= a1;
        #pragma unroll
        for (int ni = 0; ni < 8; ni++) {
            oacc[ni][0] *= a0; oacc[ni][1] *= a0;
            oacc[ni][2] *= a1; oacc[ni][3] *= a1;
        }

        // ---- P = exp(S - m), as A-fragments ----
        uint32_t phi[4][4], plo[4][4];
        #pragma unroll
        for (int kt = 0; kt < 4; kt++) {
            float p00 = __expf(sacc[2*kt][0]   - mn0);
            float p01 = __expf(sacc[2*kt][1]   - mn0);
            float p02 = __expf(sacc[2*kt][2]   - mn1);
            float p03 = __expf(sacc[2*kt][3]   - mn1);
            float p10 = __expf(sacc[2*kt+1][0] - mn0);
            float p11 = __expf(sacc[2*kt+1][1] - mn0);
            float p12 = __expf(sacc[2*kt+1][2] - mn1);
            float p13 = __expf(sacc[2*kt+1][3] - mn1);
            l0 += p00 + p01 + p10 + p11;
            l1 += p02 + p03 + p12 + p13;
            split2(p00, p01, phi[kt][0], plo[kt][0]);
            split2(p02, p03, phi[kt][1], plo[kt][1]);
            split2(p10, p11, phi[kt][2], plo[kt][2]);
            split2(p12, p13, phi[kt][3], plo[kt][3]);
        }

        // ---- O += P V via ldmatrix fragments ----
        #pragma unroll
        for (int kt = 0; kt < 4; kt++) {
            #pragma unroll
            for (int ndp = 0; ndp < 4; ndp++) {
                int d = ndp * 16 + lm_rowB;
                uint32_t off = (uint32_t)(d * 144 + (kt * 16 + lm_kofB) * 2);
                uint32_t vh0, vh1, vh2, vh3, vl0, vl1, vl2, vl3;
                LDSM4(vh0, vh1, vh2, vh3, VhiB + off);
                LDSM4(vl0, vl1, vl2, vl3, VloB + off);
                MMA_F16(oacc[2*ndp],   plo[kt][0], plo[kt][1], plo[kt][2], plo[kt][3], vh0, vh1);
                MMA_F16(oacc[2*ndp],   phi[kt][0], phi[kt][1], phi[kt][2], phi[kt][3], vl0, vl1);
                MMA_F16(oacc[2*ndp],   phi[kt][0], phi[kt][1], phi[kt][2], phi[kt][3], vh0, vh1);
                MMA_F16(oacc[2*ndp+1], plo[kt][0], plo[kt][1], plo[kt][2], plo[kt][3], vh2, vh3);
                MMA_F16(oacc[2*ndp+1], phi[kt][0], phi[kt][1], phi[kt][2], phi[kt][3], vl2, vl3);
                MMA_F16(oacc[2*ndp+1], phi[kt][0], phi[kt][1], phi[kt][2], phi[kt][3], vh2, vh3);
            }
        }
        m0 = mn0; m1 = mn1;
        __syncthreads();
    }

    l0 += __shfl_xor_sync(0xffffffffu, l0, 1);
    l0 += __shfl_xor_sync(0xffffffffu, l0, 2);
    l1 += __shfl_xor_sync(0xffffffffu, l1, 1);
    l1 += __shfl_xor_sync(0xffffffffu, l1, 2);
    float i0 = 1.0f / l0, i1 = 1.0f / l1;

    #pragma unroll
    for (int nd = 0; nd < 8; nd++) {
        int col = h * DHEAD + nd * 8 + 2 * gc;
        *(float2*)(out + (size_t)(b * SEQ + q0 + gr) * INNER + col) =
            make_float2(oacc[nd][0] * i0, oacc[nd][1] * i0);
        *(float2*)(out + (size_t)(b * SEQ + q0 + 8 + gr) * INNER + col) =
            make_float2(oacc[nd][2] * i1, oacc[nd][3] * i1);
    }
}

// ===========================================================================
extern "C" void kernel_launch(void* const* d_in, const int* in_sizes, int n_in,
                              void* d_out, int out_size)
{
    const float* x     = (const float*)d_in[0];
    const float* ln_g  = (const float*)d_in[1];
    const float* q_g   = (const float*)d_in[2];
    const float* k_g   = (const float*)d_in[3];
    const float* w_qkv = (const float*)d_in[4];
    const float* w_out = (const float*)d_in[5];
    float* out = (float*)d_out;

    float *xn, *qkv, *att;
    cudaGetSymbolAddress((void**)&xn,  g_xn);
    cudaGetSymbolAddress((void**)&qkv, g_qkv);
    cudaGetSymbolAddress((void**)&att, g_att);

    ln_kernel<<<ROWS, 256>>>(x, ln_g, xn);

    gemm_f16x3<<<dim3(3 * INNER / 128, ROWS / 128), 256>>>(xn, w_qkv, qkv,
                                                           ROWS, 3 * INNER, DIM);

    rms_kernel<<<ROWS, 512>>>(qkv, q_g, k_g);

    attn_mma<<<dim3(BATCH * HEADS, SEQ / 128), 256>>>(qkv, att);

    gemm_f16x3<<<dim3(DIM / 128, ROWS / 128), 256>>>(att, w_out, out,
                                                     ROWS, DIM, INNER);
}

// round 16
// speedup vs baseline: 2.8873x; 1.2207x over previous
#include <cuda_runtime.h>
#include <cuda_fp16.h>
#include <math.h>
#include <stdint.h>

#define DIM     1024
#define HEADS   16
#define DHEAD   64
#define INNER   1024
#define SEQ     1024
#define BATCH   8
#define ROWS    (BATCH*SEQ)   // 8192

// ---------------------------------------------------------------------------
// Scratch (allocation-free rule: __device__ globals)
// ---------------------------------------------------------------------------
__device__ float  g_qkv [ROWS * 3 * INNER];          // GEMM1 output (fp32)
__device__ __half g_xnh [ROWS * DIM],      g_xnl [ROWS * DIM];       // LN out
__device__ __half g_wh  [3*INNER * DIM],   g_wl  [3*INNER * DIM];    // w_qkv^T [n][k]
__device__ __half g_w2h [DIM * INNER],     g_w2l [DIM * INNER];      // w_out^T [n][k]
__device__ __half g_qkvh[ROWS * 3 * INNER], g_qkvl[ROWS * 3 * INNER];
__device__ __half g_atth[ROWS * INNER],    g_attl[ROWS * INNER];

// ---------------------------------------------------------------------------
// helpers
// ---------------------------------------------------------------------------
__device__ __forceinline__ uint32_t pack2(float x, float y) {
    __half2 h = __floats2half2_rn(x, y);
    return *reinterpret_cast<uint32_t*>(&h);
}
__device__ __forceinline__ void split2(float x, float y, uint32_t& hi, uint32_t& lo) {
    float hx = __half2float(__float2half_rn(x));
    float hy = __half2float(__float2half_rn(y));
    hi = pack2(hx, hy);
    lo = pack2(x - hx, y - hy);
}
__device__ __forceinline__ uint32_t cvta_s(const void* p) {
    uint32_t a;
    asm("{ .reg .u64 t; cvta.to.shared.u64 t, %1; cvt.u32.u64 %0, t; }" : "=r"(a) : "l"(p));
    return a;
}

#define MMA_F16(c, A0, A1, A2, A3, B0, B1)                                    \
    asm volatile("mma.sync.aligned.m16n8k16.row.col.f32.f16.f16.f32 "         \
                 "{%0,%1,%2,%3}, {%4,%5,%6,%7}, {%8,%9}, {%0,%1,%2,%3};"      \
                 : "+f"((c)[0]), "+f"((c)[1]), "+f"((c)[2]), "+f"((c)[3])     \
                 : "r"(A0), "r"(A1), "r"(A2), "r"(A3), "r"(B0), "r"(B1))

#define LDSM4(r0, r1, r2, r3, a)                                              \
    asm volatile("ldmatrix.sync.aligned.m8n8.x4.shared.b16 {%0,%1,%2,%3}, [%4];" \
                 : "=r"(r0), "=r"(r1), "=r"(r2), "=r"(r3) : "r"(a))
#define LDSM4T(r0, r1, r2, r3, a)                                             \
    asm volatile("ldmatrix.sync.aligned.m8n8.x4.trans.shared.b16 {%0,%1,%2,%3}, [%4];" \
                 : "=r"(r0), "=r"(r1), "=r"(r2), "=r"(r3) : "r"(a))

// ===========================================================================
// prep_w: W[K][N] fp32 -> Bh/Bl[N][K] halves (transposed, hi/lo split)
// ===========================================================================
__global__ __launch_bounds__(256) void prep_w(const float* __restrict__ W,
                                              __half* __restrict__ Bh,
                                              __half* __restrict__ Bl,
                                              int N, int K)
{
    __shared__ float t[32][33];
    int n0 = blockIdx.x * 32, k0 = blockIdx.y * 32;
    int tx = threadIdx.x & 31, ty = threadIdx.x >> 5;   // ty: 0..7
    #pragma unroll
    for (int j = 0; j < 4; j++) {
        int k = ty + j * 8;
        t[k][tx] = W[(size_t)(k0 + k) * N + n0 + tx];
    }
    __syncthreads();
    #pragma unroll
    for (int j = 0; j < 4; j++) {
        int n = ty + j * 8;
        float v = t[tx][n];
        __half hh = __float2half_rn(v);
        size_t o = (size_t)(n0 + n) * K + k0 + tx;
        Bh[o] = hh;
        Bl[o] = __float2half_rn(v - __half2float(hh));
    }
}

// ===========================================================================
// 3xFP16 mma GEMM, pure-copy fills: C[M,N] = A*B^T with A[m][k], B[n][k]
// given as pre-split hi/lo half arrays (row stride = K).
// 128x128x32 CTA tile, 256 thr, 64x32 warp tile, 2 CTAs/SM.
// ===========================================================================
#define ASTR 20   // b32 per row -> 80 bytes (64B data + 16B pad)

__global__ __launch_bounds__(256, 2) void gemm_f16x3(const __half* __restrict__ Ah,
                                                     const __half* __restrict__ Al,
                                                     const __half* __restrict__ Bh,
                                                     const __half* __restrict__ Bl,
                                                     float* __restrict__ C,
                                                     int M, int N, int K)
{
    __shared__ __align__(16) uint32_t Ahi[128 * ASTR];
    __shared__ __align__(16) uint32_t Alo[128 * ASTR];
    __shared__ __align__(16) uint32_t Bhi[128 * ASTR];
    __shared__ __align__(16) uint32_t Blo[128 * ASTR];

    const int tid  = threadIdx.x;
    const int lane = tid & 31;
    const int wid  = tid >> 5;
    const int mw   = wid >> 2;
    const int nw   = wid & 3;
    const int brow = blockIdx.y * 128;
    const int bcol = blockIdx.x * 128;
    const int gr   = lane >> 2;
    const int gc   = lane & 3;

    const uint32_t AhiB = cvta_s(Ahi), AloB = cvta_s(Alo);
    const uint32_t BhiB = cvta_s(Bhi), BloB = cvta_s(Blo);

    const int lm_row  = (lane & 15);
    const int lm_kofA = (lane >> 4) << 3;
    const int lm_rowB = (lane & 7) + ((lane >> 4) << 3);
    const int lm_kofB = ((lane >> 3) & 1) << 3;

    float acc[4][4][4];
    #pragma unroll
    for (int i = 0; i < 4; i++)
        #pragma unroll
        for (int j = 0; j < 4; j++)
            #pragma unroll
            for (int c = 0; c < 4; c++) acc[i][j][c] = 0.f;

    const int f_row = tid >> 2;      // 0..63 (row step 64)
    const int f_c   = tid & 3;       // uint4 group (8 halves)

    for (int k0 = 0; k0 < K; k0 += 32) {
        // ---- pure-copy fills: 2 uint4 per thread per array ----
        #pragma unroll
        for (int j = 0; j < 2; j++) {
            int row = f_row + j * 64;
            size_t gsrc = (size_t)(brow + row) * K + k0 + f_c * 8;
            ((uint4*)((char*)Ahi + row * 80))[f_c] = *(const uint4*)(Ah + gsrc);
            ((uint4*)((char*)Alo + row * 80))[f_c] = *(const uint4*)(Al + gsrc);
            size_t bsrc = (size_t)(bcol + row) * K + k0 + f_c * 8;
            ((uint4*)((char*)Bhi + row * 80))[f_c] = *(const uint4*)(Bh + bsrc);
            ((uint4*)((char*)Blo + row * 80))[f_c] = *(const uint4*)(Bl + bsrc);
        }
        __syncthreads();

        #pragma unroll
        for (int ks = 0; ks < 2; ks++) {
            uint32_t bh[4][2], bl[4][2];
            #pragma unroll
            for (int np = 0; np < 2; np++) {
                int n  = nw * 32 + np * 16 + lm_rowB;
                uint32_t off = (uint32_t)(n * 80 + (ks * 16 + lm_kofB) * 2);
                LDSM4(bh[2*np][0], bh[2*np][1], bh[2*np+1][0], bh[2*np+1][1], BhiB + off);
                LDSM4(bl[2*np][0], bl[2*np][1], bl[2*np+1][0], bl[2*np+1][1], BloB + off);
            }
            #pragma unroll
            for (int mi = 0; mi < 4; mi++) {
                int r = mw * 64 + mi * 16 + lm_row;
                uint32_t off = (uint32_t)(r * 80 + (ks * 16 + lm_kofA) * 2);
                uint32_t ah0, ah1, ah2, ah3, al0, al1, al2, al3;
                LDSM4(ah0, ah1, ah2, ah3, AhiB + off);
                LDSM4(al0, al1, al2, al3, AloB + off);
                #pragma unroll
                for (int ni = 0; ni < 4; ni++) {
                    MMA_F16(acc[mi][ni], al0, al1, al2, al3, bh[ni][0], bh[ni][1]);
                    MMA_F16(acc[mi][ni], ah0, ah1, ah2, ah3, bl[ni][0], bl[ni][1]);
                    MMA_F16(acc[mi][ni], ah0, ah1, ah2, ah3, bh[ni][0], bh[ni][1]);
                }
            }
        }
        __syncthreads();
    }

    #pragma unroll
    for (int mi = 0; mi < 4; mi++) {
        int row = brow + mw * 64 + mi * 16 + gr;
        #pragma unroll
        for (int ni = 0; ni < 4; ni++) {
            int col = bcol + nw * 32 + ni * 8 + gc * 2;
            *(float2*)(C + (size_t)row * N + col) =
                make_float2(acc[mi][ni][0], acc[mi][ni][1]);
            *(float2*)(C + (size_t)(row + 8) * N + col) =
                make_float2(acc[mi][ni][2], acc[mi][ni][3]);
        }
    }
}

// ===========================================================================
// LayerNorm -> hi/lo half output
// ===========================================================================
__global__ __launch_bounds__(256) void ln_kernel(const float* __restrict__ x,
                                                 const float* __restrict__ gamma)
{
    int row = blockIdx.x;
    const float4* xr = (const float4*)(x + (size_t)row * DIM);
    float4 v = xr[threadIdx.x];
    float s  = v.x + v.y + v.z + v.w;
    float ss = v.x*v.x + v.y*v.y + v.z*v.z + v.w*v.w;
    #pragma unroll
    for (int o = 16; o > 0; o >>= 1) {
        s  += __shfl_down_sync(0xffffffffu, s,  o);
        ss += __shfl_down_sync(0xffffffffu, ss, o);
    }
    __shared__ float sh_s[8], sh_ss[8];
    int w = threadIdx.x >> 5, lane = threadIdx.x & 31;
    if (lane == 0) { sh_s[w] = s; sh_ss[w] = ss; }
    __syncthreads();
    if (w == 0) {
        s  = (lane < 8) ? sh_s[lane]  : 0.f;
        ss = (lane < 8) ? sh_ss[lane] : 0.f;
        #pragma unroll
        for (int o = 4; o > 0; o >>= 1) {
            s  += __shfl_down_sync(0xffffffffu, s,  o);
            ss += __shfl_down_sync(0xffffffffu, ss, o);
        }
        if (lane == 0) { sh_s[0] = s; sh_ss[0] = ss; }
    }
    __syncthreads();
    float mu  = sh_s[0]  * (1.0f / DIM);
    float var = sh_ss[0] * (1.0f / DIM) - mu * mu;
    float inv = rsqrtf(var + 1e-5f);
    float4 g = ((const float4*)gamma)[threadIdx.x];
    float r0 = (v.x - mu) * inv * g.x;
    float r1 = (v.y - mu) * inv * g.y;
    float r2 = (v.z - mu) * inv * g.z;
    float r3 = (v.w - mu) * inv * g.w;
    uint32_t h0, l0, h1, l1;
    split2(r0, r1, h0, l0);
    split2(r2, r3, h1, l1);
    size_t o = (size_t)row * DIM + threadIdx.x * 4;
    *(uint2*)&g_xnh[o] = make_uint2(h0, h1);
    *(uint2*)&g_xnl[o] = make_uint2(l0, l1);
}

// ===========================================================================
// rmsconv: per-head RMS on q,k + hi/lo half conversion of q,k,v
// ===========================================================================
__global__ __launch_bounds__(512) void rmsconv(const float* __restrict__ qkv,
                                               const float* __restrict__ qg,
                                               const float* __restrict__ kg)
{
    int row    = blockIdx.x;
    int unit   = threadIdx.x >> 4;
    int lane16 = threadIdx.x & 15;
    int qk     = unit >> 4;
    int head   = unit & 15;

    const float* p = qkv + (size_t)row * (3 * INNER) + qk * INNER + head * DHEAD;
    float4 v = ((const float4*)p)[lane16];
    float ss = v.x*v.x + v.y*v.y + v.z*v.z + v.w*v.w;
    #pragma unroll
    for (int o = 8; o > 0; o >>= 1)
        ss += __shfl_xor_sync(0xffffffffu, ss, o, 16);
    float n = sqrtf(ss);
    float scale = 8.0f / fmaxf(n, 1e-12f);

    const float* g = (qk ? kg : qg) + head * DHEAD + lane16 * 4;
    float r0 = v.x * scale * g[0];
    float r1 = v.y * scale * g[1];
    float r2 = v.z * scale * g[2];
    float r3 = v.w * scale * g[3];
    uint32_t h0, l0, h1, l1;
    split2(r0, r1, h0, l0);
    split2(r2, r3, h1, l1);
    size_t o = (size_t)row * (3 * INNER) + qk * INNER + head * DHEAD + lane16 * 4;
    *(uint2*)&g_qkvh[o] = make_uint2(h0, h1);
    *(uint2*)&g_qkvl[o] = make_uint2(l0, l1);

    // v: plain convert (512 threads x 2 floats = 1024)
    size_t vo = (size_t)row * (3 * INNER) + 2 * INNER + threadIdx.x * 2;
    float2 vv = *(const float2*)(qkv + vo);
    uint32_t vh, vl;
    split2(vv.x, vv.y, vh, vl);
    *(uint32_t*)&g_qkvh[vo] = vh;
    *(uint32_t*)&g_qkvl[vo] = vl;
}

// ===========================================================================
// MMA flash attention (FA-2): pure-copy K/V fill + ldmatrix(.trans) fragments.
// 256 thr, 8 warps x 16 q-rows. 64-key tiles, 3xFP16 mma.
// K and V both stored [key][d] halves, stride 144 B; V fragments via trans.
// Epilogue writes hi/lo half output for GEMM2.
// ===========================================================================
#define KSTR 36

__global__ __launch_bounds__(256) void attn_mma()
{
    __shared__ __align__(16) uint32_t Khi[64 * KSTR];
    __shared__ __align__(16) uint32_t Klo[64 * KSTR];
    __shared__ __align__(16) uint32_t Vhi[64 * KSTR];
    __shared__ __align__(16) uint32_t Vlo[64 * KSTR];

    const int tid  = threadIdx.x;
    const int lane = tid & 31;
    const int wid  = tid >> 5;
    const int gr   = lane >> 2;
    const int gc   = lane & 3;

    const uint32_t KhiB = cvta_s(Khi), KloB = cvta_s(Klo);
    const uint32_t VhiB = cvta_s(Vhi), VloB = cvta_s(Vlo);
    const int lm_rowB = (lane & 7) + ((lane >> 4) << 3);   // non-trans (K)
    const int lm_kofB = ((lane >> 3) & 1) << 3;
    const int tr_key  = (((lane >> 3) & 1) << 3) + (lane & 7);  // trans (V)
    const int tr_d    = (lane >> 4) << 3;

    const int bh = blockIdx.x;
    const int b  = bh >> 4, h = bh & 15;
    const int q0 = blockIdx.y * 128 + wid * 16;
    const size_t rbase = (size_t)b * SEQ;

    // ---- Q fragments: direct LDG of pre-split halves ----
    uint32_t qhi[4][4], qlo[4][4];
    {
        const __half* qh = g_qkvh + rbase * (3 * INNER) + h * DHEAD;
        const __half* ql = g_qkvl + rbase * (3 * INNER) + h * DHEAD;
        #pragma unroll
        for (int ks = 0; ks < 4; ks++) {
            int r0 = q0 + gr, r1 = q0 + 8 + gr;
            int d0 = ks * 16 + 2 * gc, d1 = d0 + 8;
            qhi[ks][0] = *(const uint32_t*)(qh + (size_t)r0 * (3*INNER) + d0);
            qhi[ks][1] = *(const uint32_t*)(qh + (size_t)r1 * (3*INNER) + d0);
            qhi[ks][2] = *(const uint32_t*)(qh + (size_t)r0 * (3*INNER) + d1);
            qhi[ks][3] = *(const uint32_t*)(qh + (size_t)r1 * (3*INNER) + d1);
            qlo[ks][0] = *(const uint32_t*)(ql + (size_t)r0 * (3*INNER) + d0);
            qlo[ks][1] = *(const uint32_t*)(ql + (size_t)r1 * (3*INNER) + d0);
            qlo[ks][2] = *(const uint32_t*)(ql + (size_t)r0 * (3*INNER) + d1);
            qlo[ks][3] = *(const uint32_t*)(ql + (size_t)r1 * (3*INNER) + d1);
        }
    }

    float oacc[8][4];
    #pragma unroll
    for (int i = 0; i < 8; i++)
        #pragma unroll
        for (int c = 0; c < 4; c++) oacc[i][c] = 0.f;
    float m0 = -INFINITY, m1 = -INFINITY, l0 = 0.f, l1 = 0.f;

    // fill mapping: thread -> key = tid>>2, two uint4 groups (t&3, (t&3)+4)
    const int f_key = tid >> 2;
    const int f_c   = tid & 3;
    const size_t khsrc0 = (rbase) * (3 * INNER) + INNER + h * DHEAD;      // + key*3072
    const size_t vhsrc0 = (rbase) * (3 * INNER) + 2 * INNER + h * DHEAD;

    uint4 kh4[2], kl4[2], vh4[2], vl4[2];
    #pragma unroll
    for (int j = 0; j < 2; j++) {
        size_t ko = khsrc0 + (size_t)f_key * (3 * INNER) + (f_c + 4 * j) * 8;
        size_t vo = vhsrc0 + (size_t)f_key * (3 * INNER) + (f_c + 4 * j) * 8;
        kh4[j] = *(const uint4*)(g_qkvh + ko);
        kl4[j] = *(const uint4*)(g_qkvl + ko);
        vh4[j] = *(const uint4*)(g_qkvh + vo);
        vl4[j] = *(const uint4*)(g_qkvl + vo);
    }

    for (int n0 = 0; n0 < SEQ; n0 += 64) {
        // ---- STS tile from registers (pure copy) ----
        #pragma unroll
        for (int j = 0; j < 2; j++) {
            ((uint4*)((char*)Khi + f_key * 144))[f_c + 4 * j] = kh4[j];
            ((uint4*)((char*)Klo + f_key * 144))[f_c + 4 * j] = kl4[j];
            ((uint4*)((char*)Vhi + f_key * 144))[f_c + 4 * j] = vh4[j];
            ((uint4*)((char*)Vlo + f_key * 144))[f_c + 4 * j] = vl4[j];
        }
        __syncthreads();

        // ---- prefetch next tile ----
        if (n0 + 64 < SEQ) {
            #pragma unroll
            for (int j = 0; j < 2; j++) {
                size_t ko = khsrc0 + (size_t)(n0 + 64 + f_key) * (3 * INNER) + (f_c + 4 * j) * 8;
                size_t vo = vhsrc0 + (size_t)(n0 + 64 + f_key) * (3 * INNER) + (f_c + 4 * j) * 8;
                kh4[j] = *(const uint4*)(g_qkvh + ko);
                kl4[j] = *(const uint4*)(g_qkvl + ko);
                vh4[j] = *(const uint4*)(g_qkvh + vo);
                vl4[j] = *(const uint4*)(g_qkvl + vo);
            }
        }

        // ---- S = Q K^T ----
        float sacc[8][4];
        #pragma unroll
        for (int i = 0; i < 8; i++)
            #pragma unroll
            for (int c = 0; c < 4; c++) sacc[i][c] = 0.f;

        #pragma unroll
        for (int ks = 0; ks < 4; ks++) {
            #pragma unroll
            for (int np = 0; np < 4; np++) {
                int n = np * 16 + lm_rowB;
                uint32_t off = (uint32_t)(n * 144 + (ks * 16 + lm_kofB) * 2);
                uint32_t kh0, kh1, kh2, kh3, kl0, kl1, kl2, kl3;
                LDSM4(kh0, kh1, kh2, kh3, KhiB + off);
                LDSM4(kl0, kl1, kl2, kl3, KloB + off);
                MMA_F16(sacc[2*np],   qlo[ks][0], qlo[ks][1], qlo[ks][2], qlo[ks][3], kh0, kh1);
                MMA_F16(sacc[2*np],   qhi[ks][0], qhi[ks][1], qhi[ks][2], qhi[ks][3], kl0, kl1);
                MMA_F16(sacc[2*np],   qhi[ks][0], qhi[ks][1], qhi[ks][2], qhi[ks][3], kh0, kh1);
                MMA_F16(sacc[2*np+1], qlo[ks][0], qlo[ks][1], qlo[ks][2], qlo[ks][3], kh2, kh3);
                MMA_F16(sacc[2*np+1], qhi[ks][0], qhi[ks][1], qhi[ks][2], qhi[ks][3], kl2, kl3);
                MMA_F16(sacc[2*np+1], qhi[ks][0], qhi[ks][1], qhi[ks][2], qhi[ks][3], kh2, kh3);
            }
        }

        // ---- online softmax ----
        float t0 = -INFINITY, t1 = -INFINITY;
        #pragma unroll
        for (int ni = 0; ni < 8; ni++) {
            t0 = fmaxf(t0, fmaxf(sacc[ni][0], sacc[ni][1]));
            t1 = fmaxf(t1, fmaxf(sacc[ni][2], sacc[ni][3]));
        }
        t0 = fmaxf(t0, __shfl_xor_sync(0xffffffffu, t0, 1));
        t0 = fmaxf(t0, __shfl_xor_sync(0xffffffffu, t0, 2));
        t1 = fmaxf(t1, __shfl_xor_sync(0xffffffffu, t1, 1));
        t1 = fmaxf(t1, __shfl_xor_sync(0xffffffffu, t1, 2));
        float mn0 = fmaxf(m0, t0), mn1 = fmaxf(m1, t1);
        float a0 = __expf(m0 - mn0), a1 = __expf(m1 - mn1);
        l0 *= a0; l1 *= a1;
        #pragma unroll
        for (int ni = 0; ni < 8; ni++) {
            oacc[ni][0] *= a0; oacc[ni][1] *= a0;
            oacc[ni][2] *= a1; oacc[ni][3] *= a1;
        }

        // ---- P = exp(S - m), as A-fragments ----
        uint32_t phi[4][4], plo[4][4];
        #pragma unroll
        for (int kt = 0; kt < 4; kt++) {
            float p00 = __expf(sacc[2*kt][0]   - mn0);
            float p01 = __expf(sacc[2*kt][1]   - mn0);
            float p02 = __expf(sacc[2*kt][2]   - mn1);
            float p03 = __expf(sacc[2*kt][3]   - mn1);
            float p10 = __expf(sacc[2*kt+1][0] - mn0);
            float p11 = __expf(sacc[2*kt+1][1] - mn0);
            float p12 = __expf(sacc[2*kt+1][2] - mn1);
            float p13 = __expf(sacc[2*kt+1][3] - mn1);
            l0 += p00 + p01 + p10 + p11;
            l1 += p02 + p03 + p12 + p13;
            split2(p00, p01, phi[kt][0], plo[kt][0]);
            split2(p02, p03, phi[kt][1], plo[kt][1]);
            split2(p10, p11, phi[kt][2], plo[kt][2]);
            split2(p12, p13, phi[kt][3], plo[kt][3]);
        }

        // ---- O += P V via ldmatrix.trans on [key][d] tile ----
        #pragma unroll
        for (int kt = 0; kt < 4; kt++) {
            #pragma unroll
            for (int ndp = 0; ndp < 4; ndp++) {
                uint32_t off = (uint32_t)((kt * 16 + tr_key) * 144
                                          + (ndp * 16 + tr_d) * 2);
                uint32_t vh0, vh1, vh2, vh3, vl0, vl1, vl2, vl3;
                LDSM4T(vh0, vh1, vh2, vh3, VhiB + off);
                LDSM4T(vl0, vl1, vl2, vl3, VloB + off);
                MMA_F16(oacc[2*ndp],   plo[kt][0], plo[kt][1], plo[kt][2], plo[kt][3], vh0, vh1);
                MMA_F16(oacc[2*ndp],   phi[kt][0], phi[kt][1], phi[kt][2], phi[kt][3], vl0, vl1);
                MMA_F16(oacc[2*ndp],   phi[kt][0], phi[kt][1], phi[kt][2], phi[kt][3], vh0, vh1);
                MMA_F16(oacc[2*ndp+1], plo[kt][0], plo[kt][1], plo[kt][2], plo[kt][3], vh2, vh3);
                MMA_F16(oacc[2*ndp+1], phi[kt][0], phi[kt][1], phi[kt][2], phi[kt][3], vl2, vl3);
                MMA_F16(oacc[2*ndp+1], phi[kt][0], phi[kt][1], phi[kt][2], phi[kt][3], vh2, vh3);
            }
        }
        m0 = mn0; m1 = mn1;
        __syncthreads();
    }

    l0 += __shfl_xor_sync(0xffffffffu, l0, 1);
    l0 += __shfl_xor_sync(0xffffffffu, l0, 2);
    l1 += __shfl_xor_sync(0xffffffffu, l1, 1);
    l1 += __shfl_xor_sync(0xffffffffu, l1, 2);
    float i0 = 1.0f / l0, i1 = 1.0f / l1;

    // ---- epilogue: write hi/lo halves for GEMM2 A ----
    #pragma unroll
    for (int nd = 0; nd < 8; nd++) {
        int col = h * DHEAD + nd * 8 + 2 * gc;
        size_t o0 = (rbase + q0 + gr) * INNER + col;
        size_t o1 = (rbase + q0 + 8 + gr) * INNER + col;
        uint32_t h0, lo0, h1, lo1;
        split2(oacc[nd][0] * i0, oacc[nd][1] * i0, h0, lo0);
        split2(oacc[nd][2] * i1, oacc[nd][3] * i1, h1, lo1);
        *(uint32_t*)&g_atth[o0] = h0;
        *(uint32_t*)&g_attl[o0] = lo0;
        *(uint32_t*)&g_atth[o1] = h1;
        *(uint32_t*)&g_attl[o1] = lo1;
    }
}

// ===========================================================================
extern "C" void kernel_launch(void* const* d_in, const int* in_sizes, int n_in,
                              void* d_out, int out_size)
{
    const float* x     = (const float*)d_in[0];
    const float* ln_g  = (const float*)d_in[1];
    const float* q_g   = (const float*)d_in[2];
    const float* k_g   = (const float*)d_in[3];
    const float* w_qkv = (const float*)d_in[4];
    const float* w_out = (const float*)d_in[5];
    float* out = (float*)d_out;

    float  *qkv;
    __half *xnh, *xnl, *wh, *wl, *w2h, *w2l, *atth, *attl;
    cudaGetSymbolAddress((void**)&qkv,  g_qkv);
    cudaGetSymbolAddress((void**)&xnh,  g_xnh);
    cudaGetSymbolAddress((void**)&xnl,  g_xnl);
    cudaGetSymbolAddress((void**)&wh,   g_wh);
    cudaGetSymbolAddress((void**)&wl,   g_wl);
    cudaGetSymbolAddress((void**)&w2h,  g_w2h);
    cudaGetSymbolAddress((void**)&w2l,  g_w2l);
    cudaGetSymbolAddress((void**)&atth, g_atth);
    cudaGetSymbolAddress((void**)&attl, g_attl);

    prep_w<<<dim3(3 * INNER / 32, DIM / 32), 256>>>(w_qkv, wh, wl, 3 * INNER, DIM);
    prep_w<<<dim3(DIM / 32, INNER / 32), 256>>>(w_out, w2h, w2l, DIM, INNER);

    ln_kernel<<<ROWS, 256>>>(x, ln_g);

    gemm_f16x3<<<dim3(3 * INNER / 128, ROWS / 128), 256>>>(
        xnh, xnl, wh, wl, qkv, ROWS, 3 * INNER, DIM);

    rmsconv<<<ROWS, 512>>>(qkv, q_g, k_g);

    attn_mma<<<dim3(BATCH * HEADS, SEQ / 128), 256>>>();

    gemm_f16x3<<<dim3(DIM / 128, ROWS / 128), 256>>>(
        atth, attl, w2h, w2l, out, ROWS, DIM, INNER);
}

// round 17
// speedup vs baseline: 2.8914x; 1.0014x over previous
#include <cuda_runtime.h>
#include <cuda_fp16.h>
#include <math.h>
#include <stdint.h>

#define DIM     1024
#define HEADS   16
#define DHEAD   64
#define INNER   1024
#define SEQ     1024
#define BATCH   8
#define ROWS    (BATCH*SEQ)   // 8192

// ---------------------------------------------------------------------------
// Scratch (allocation-free rule: __device__ globals)
// ---------------------------------------------------------------------------
__device__ float  g_qkv [ROWS * 3 * INNER];          // GEMM1 output (fp32)
__device__ __half g_xnh [ROWS * DIM],      g_xnl [ROWS * DIM];       // LN out
__device__ __half g_wh  [3*INNER * DIM],   g_wl  [3*INNER * DIM];    // w_qkv^T [n][k]
__device__ __half g_w2h [DIM * INNER],     g_w2l [DIM * INNER];      // w_out^T [n][k]
__device__ __half g_qkvh[ROWS * 3 * INNER], g_qkvl[ROWS * 3 * INNER];
__device__ __half g_atth[ROWS * INNER],    g_attl[ROWS * INNER];

// ---------------------------------------------------------------------------
// helpers
// ---------------------------------------------------------------------------
__device__ __forceinline__ uint32_t pack2(float x, float y) {
    __half2 h = __floats2half2_rn(x, y);
    return *reinterpret_cast<uint32_t*>(&h);
}
__device__ __forceinline__ void split2(float x, float y, uint32_t& hi, uint32_t& lo) {
    float hx = __half2float(__float2half_rn(x));
    float hy = __half2float(__float2half_rn(y));
    hi = pack2(hx, hy);
    lo = pack2(x - hx, y - hy);
}
__device__ __forceinline__ uint32_t cvta_s(const void* p) {
    uint32_t a;
    asm("{ .reg .u64 t; cvta.to.shared.u64 t, %1; cvt.u32.u64 %0, t; }" : "=r"(a) : "l"(p));
    return a;
}

#define MMA_F16(c, A0, A1, A2, A3, B0, B1)                                    \
    asm volatile("mma.sync.aligned.m16n8k16.row.col.f32.f16.f16.f32 "         \
                 "{%0,%1,%2,%3}, {%4,%5,%6,%7}, {%8,%9}, {%0,%1,%2,%3};"      \
                 : "+f"((c)[0]), "+f"((c)[1]), "+f"((c)[2]), "+f"((c)[3])     \
                 : "r"(A0), "r"(A1), "r"(A2), "r"(A3), "r"(B0), "r"(B1))

#define LDSM4(r0, r1, r2, r3, a)                                              \
    asm volatile("ldmatrix.sync.aligned.m8n8.x4.shared.b16 {%0,%1,%2,%3}, [%4];" \
                 : "=r"(r0), "=r"(r1), "=r"(r2), "=r"(r3) : "r"(a))
#define LDSM4T(r0, r1, r2, r3, a)                                             \
    asm volatile("ldmatrix.sync.aligned.m8n8.x4.trans.shared.b16 {%0,%1,%2,%3}, [%4];" \
                 : "=r"(r0), "=r"(r1), "=r"(r2), "=r"(r3) : "r"(a))

// ===========================================================================
// prep_w: W[K][N] fp32 -> Bh/Bl[N][K] halves (transposed, hi/lo split)
// ===========================================================================
__global__ __launch_bounds__(256) void prep_w(const float* __restrict__ W,
                                              __half* __restrict__ Bh,
                                              __half* __restrict__ Bl,
                                              int N, int K)
{
    __shared__ float t[32][33];
    int n0 = blockIdx.x * 32, k0 = blockIdx.y * 32;
    int tx = threadIdx.x & 31, ty = threadIdx.x >> 5;   // ty: 0..7
    #pragma unroll
    for (int j = 0; j < 4; j++) {
        int k = ty + j * 8;
        t[k][tx] = W[(size_t)(k0 + k) * N + n0 + tx];
    }
    __syncthreads();
    #pragma unroll
    for (int j = 0; j < 4; j++) {
        int n = ty + j * 8;
        float v = t[tx][n];
        __half hh = __float2half_rn(v);
        size_t o = (size_t)(n0 + n) * K + k0 + tx;
        Bh[o] = hh;
        Bl[o] = __float2half_rn(v - __half2float(hh));
    }
}

// ===========================================================================
// 3xFP16 mma GEMM, pure-copy fills: C[M,N] = A*B^T with A[m][k], B[n][k]
// given as pre-split hi/lo half arrays (row stride = K).
// 128x128x32 CTA tile, 256 thr, 64x32 warp tile, 2 CTAs/SM.
// ===========================================================================
#define ASTR 20   // b32 per row -> 80 bytes (64B data + 16B pad)

__global__ __launch_bounds__(256, 2) void gemm_f16x3(const __half* __restrict__ Ah,
                                                     const __half* __restrict__ Al,
                                                     const __half* __restrict__ Bh,
                                                     const __half* __restrict__ Bl,
                                                     float* __restrict__ C,
                                                     int M, int N, int K)
{
    __shared__ __align__(16) uint32_t Ahi[128 * ASTR];
    __shared__ __align__(16) uint32_t Alo[128 * ASTR];
    __shared__ __align__(16) uint32_t Bhi[128 * ASTR];
    __shared__ __align__(16) uint32_t Blo[128 * ASTR];

    const int tid  = threadIdx.x;
    const int lane = tid & 31;
    const int wid  = tid >> 5;
    const int mw   = wid >> 2;
    const int nw   = wid & 3;
    const int brow = blockIdx.y * 128;
    const int bcol = blockIdx.x * 128;
    const int gr   = lane >> 2;
    const int gc   = lane & 3;

    const uint32_t AhiB = cvta_s(Ahi), AloB = cvta_s(Alo);
    const uint32_t BhiB = cvta_s(Bhi), BloB = cvta_s(Blo);

    const int lm_row  = (lane & 15);
    const int lm_kofA = (lane >> 4) << 3;
    const int lm_rowB = (lane & 7) + ((lane >> 4) << 3);
    const int lm_kofB = ((lane >> 3) & 1) << 3;

    float acc[4][4][4];
    #pragma unroll
    for (int i = 0; i < 4; i++)
        #pragma unroll
        for (int j = 0; j < 4; j++)
            #pragma unroll
            for (int c = 0; c < 4; c++) acc[i][j][c] = 0.f;

    const int f_row = tid >> 2;      // 0..63 (row step 64)
    const int f_c   = tid & 3;       // uint4 group (8 halves)

    for (int k0 = 0; k0 < K; k0 += 32) {
        // ---- pure-copy fills: 2 uint4 per thread per array ----
        #pragma unroll
        for (int j = 0; j < 2; j++) {
            int row = f_row + j * 64;
            size_t gsrc = (size_t)(brow + row) * K + k0 + f_c * 8;
            ((uint4*)((char*)Ahi + row * 80))[f_c] = *(const uint4*)(Ah + gsrc);
            ((uint4*)((char*)Alo + row * 80))[f_c] = *(const uint4*)(Al + gsrc);
            size_t bsrc = (size_t)(bcol + row) * K + k0 + f_c * 8;
            ((uint4*)((char*)Bhi + row * 80))[f_c] = *(const uint4*)(Bh + bsrc);
            ((uint4*)((char*)Blo + row * 80))[f_c] = *(const uint4*)(Bl + bsrc);
        }
        __syncthreads();

        #pragma unroll
        for (int ks = 0; ks < 2; ks++) {
            uint32_t bh[4][2], bl[4][2];
            #pragma unroll
            for (int np = 0; np < 2; np++) {
                int n  = nw * 32 + np * 16 + lm_rowB;
                uint32_t off = (uint32_t)(n * 80 + (ks * 16 + lm_kofB) * 2);
                LDSM4(bh[2*np][0], bh[2*np][1], bh[2*np+1][0], bh[2*np+1][1], BhiB + off);
                LDSM4(bl[2*np][0], bl[2*np][1], bl[2*np+1][0], bl[2*np+1][1], BloB + off);
            }
            #pragma unroll
            for (int mi = 0; mi < 4; mi++) {
                int r = mw * 64 + mi * 16 + lm_row;
                uint32_t off = (uint32_t)(r * 80 + (ks * 16 + lm_kofA) * 2);
                uint32_t ah0, ah1, ah2, ah3, al0, al1, al2, al3;
                LDSM4(ah0, ah1, ah2, ah3, AhiB + off);
                LDSM4(al0, al1, al2, al3, AloB + off);
                #pragma unroll
                for (int ni = 0; ni < 4; ni++) {
                    MMA_F16(acc[mi][ni], al0, al1, al2, al3, bh[ni][0], bh[ni][1]);
                    MMA_F16(acc[mi][ni], ah0, ah1, ah2, ah3, bl[ni][0], bl[ni][1]);
                    MMA_F16(acc[mi][ni], ah0, ah1, ah2, ah3, bh[ni][0], bh[ni][1]);
                }
            }
        }
        __syncthreads();
    }

    #pragma unroll
    for (int mi = 0; mi < 4; mi++) {
        int row = brow + mw * 64 + mi * 16 + gr;
        #pragma unroll
        for (int ni = 0; ni < 4; ni++) {
            int col = bcol + nw * 32 + ni * 8 + gc * 2;
            *(float2*)(C + (size_t)row * N + col) =
                make_float2(acc[mi][ni][0], acc[mi][ni][1]);
            *(float2*)(C + (size_t)(row + 8) * N + col) =
                make_float2(acc[mi][ni][2], acc[mi][ni][3]);
        }
    }
}

// ===========================================================================
// LayerNorm -> hi/lo half output
// ===========================================================================
__global__ __launch_bounds__(256) void ln_kernel(const float* __restrict__ x,
                                                 const float* __restrict__ gamma)
{
    int row = blockIdx.x;
    const float4* xr = (const float4*)(x + (size_t)row * DIM);
    float4 v = xr[threadIdx.x];
    float s  = v.x + v.y + v.z + v.w;
    float ss = v.x*v.x + v.y*v.y + v.z*v.z + v.w*v.w;
    #pragma unroll
    for (int o = 16; o > 0; o >>= 1) {
        s  += __shfl_down_sync(0xffffffffu, s,  o);
        ss += __shfl_down_sync(0xffffffffu, ss, o);
    }
    __shared__ float sh_s[8], sh_ss[8];
    int w = threadIdx.x >> 5, lane = threadIdx.x & 31;
    if (lane == 0) { sh_s[w] = s; sh_ss[w] = ss; }
    __syncthreads();
    if (w == 0) {
        s  = (lane < 8) ? sh_s[lane]  : 0.f;
        ss = (lane < 8) ? sh_ss[lane] : 0.f;
        #pragma unroll
        for (int o = 4; o > 0; o >>= 1) {
            s  += __shfl_down_sync(0xffffffffu, s,  o);
            ss += __shfl_down_sync(0xffffffffu, ss, o);
        }
        if (lane == 0) { sh_s[0] = s; sh_ss[0] = ss; }
    }
    __syncthreads();
    float mu  = sh_s[0]  * (1.0f / DIM);
    float var = sh_ss[0] * (1.0f / DIM) - mu * mu;
    float inv = rsqrtf(var + 1e-5f);
    float4 g = ((const float4*)gamma)[threadIdx.x];
    float r0 = (v.x - mu) * inv * g.x;
    float r1 = (v.y - mu) * inv * g.y;
    float r2 = (v.z - mu) * inv * g.z;
    float r3 = (v.w - mu) * inv * g.w;
    uint32_t h0, l0, h1, l1;
    split2(r0, r1, h0, l0);
    split2(r2, r3, h1, l1);
    size_t o = (size_t)row * DIM + threadIdx.x * 4;
    *(uint2*)&g_xnh[o] = make_uint2(h0, h1);
    *(uint2*)&g_xnl[o] = make_uint2(l0, l1);
}

// ===========================================================================
// rmsconv: per-head RMS on q,k + hi/lo half conversion of q,k,v
// ===========================================================================
__global__ __launch_bounds__(512) void rmsconv(const float* __restrict__ qkv,
                                               const float* __restrict__ qg,
                                               const float* __restrict__ kg)
{
    int row    = blockIdx.x;
    int unit   = threadIdx.x >> 4;
    int lane16 = threadIdx.x & 15;
    int qk     = unit >> 4;
    int head   = unit & 15;

    const float* p = qkv + (size_t)row * (3 * INNER) + qk * INNER + head * DHEAD;
    float4 v = ((const float4*)p)[lane16];
    float ss = v.x*v.x + v.y*v.y + v.z*v.z + v.w*v.w;
    #pragma unroll
    for (int o = 8; o > 0; o >>= 1)
        ss += __shfl_xor_sync(0xffffffffu, ss, o, 16);
    float n = sqrtf(ss);
    float scale = 8.0f / fmaxf(n, 1e-12f);

    const float* g = (qk ? kg : qg) + head * DHEAD + lane16 * 4;
    float r0 = v.x * scale * g[0];
    float r1 = v.y * scale * g[1];
    float r2 = v.z * scale * g[2];
    float r3 = v.w * scale * g[3];
    uint32_t h0, l0, h1, l1;
    split2(r0, r1, h0, l0);
    split2(r2, r3, h1, l1);
    size_t o = (size_t)row * (3 * INNER) + qk * INNER + head * DHEAD + lane16 * 4;
    *(uint2*)&g_qkvh[o] = make_uint2(h0, h1);
    *(uint2*)&g_qkvl[o] = make_uint2(l0, l1);

    // v: plain convert (512 threads x 2 floats = 1024)
    size_t vo = (size_t)row * (3 * INNER) + 2 * INNER + threadIdx.x * 2;
    float2 vv = *(const float2*)(qkv + vo);
    uint32_t vh, vl;
    split2(vv.x, vv.y, vh, vl);
    *(uint32_t*)&g_qkvh[vo] = vh;
    *(uint32_t*)&g_qkvl[vo] = vl;
}

// ===========================================================================
// MMA flash attention (FA-2): pure-copy K/V fill + ldmatrix(.trans) fragments.
// 256 thr, 8 warps x 16 q-rows. 64-key tiles, 3xFP16 mma.
// K and V both stored [key][d] halves, stride 144 B; V fragments via trans.
// Epilogue writes hi/lo half output for GEMM2.
// ===========================================================================
#define KSTR 36

__global__ __launch_bounds__(256) void attn_mma()
{
    __shared__ __align__(16) uint32_t Khi[64 * KSTR];
    __shared__ __align__(16) uint32_t Klo[64 * KSTR];
    __shared__ __align__(16) uint32_t Vhi[64 * KSTR];
    __shared__ __align__(16) uint32_t Vlo[64 * KSTR];

    const int tid  = threadIdx.x;
    const int lane = tid & 31;
    const int wid  = tid >> 5;
    const int gr   = lane >> 2;
    const int gc   = lane & 3;

    const uint32_t KhiB = cvta_s(Khi), KloB = cvta_s(Klo);
    const uint32_t VhiB = cvta_s(Vhi), VloB = cvta_s(Vlo);
    const int lm_rowB = (lane & 7) + ((lane >> 4) << 3);   // non-trans (K)
    const int lm_kofB = ((lane >> 3) & 1) << 3;
    const int tr_key  = (((lane >> 3) & 1) << 3) + (lane & 7);  // trans (V)
    const int tr_d    = (lane >> 4) << 3;

    const int bh = blockIdx.x;
    const int b  = bh >> 4, h = bh & 15;
    const int q0 = blockIdx.y * 128 + wid * 16;
    const size_t rbase = (size_t)b * SEQ;

    // ---- Q fragments: direct LDG of pre-split halves ----
    uint32_t qhi[4][4], qlo[4][4];
    {
        const __half* qh = g_qkvh + rbase * (3 * INNER) + h * DHEAD;
        const __half* ql = g_qkvl + rbase * (3 * INNER) + h * DHEAD;
        #pragma unroll
        for (int ks = 0; ks < 4; ks++) {
            int r0 = q0 + gr, r1 = q0 + 8 + gr;
            int d0 = ks * 16 + 2 * gc, d1 = d0 + 8;
            qhi[ks][0] = *(const uint32_t*)(qh + (size_t)r0 * (3*INNER) + d0);
            qhi[ks][1] = *(const uint32_t*)(qh + (size_t)r1 * (3*INNER) + d0);
            qhi[ks][2] = *(const uint32_t*)(qh + (size_t)r0 * (3*INNER) + d1);
            qhi[ks][3] = *(const uint32_t*)(qh + (size_t)r1 * (3*INNER) + d1);
            qlo[ks][0] = *(const uint32_t*)(ql + (size_t)r0 * (3*INNER) + d0);
            qlo[ks][1] = *(const uint32_t*)(ql + (size_t)r1 * (3*INNER) + d0);
            qlo[ks][2] = *(const uint32_t*)(ql + (size_t)r0 * (3*INNER) + d1);
            qlo[ks][3] = *(const uint32_t*)(ql + (size_t)r1 * (3*INNER) + d1);
        }
    }

    float oacc[8][4];
    #pragma unroll
    for (int i = 0; i < 8; i++)
        #pragma unroll
        for (int c = 0; c < 4; c++) oacc[i][c] = 0.f;
    float m0 = -INFINITY, m1 = -INFINITY, l0 = 0.f, l1 = 0.f;

    // fill mapping: thread -> key = tid>>2, two uint4 groups (t&3, (t&3)+4)
    const int f_key = tid >> 2;
    const int f_c   = tid & 3;
    const size_t khsrc0 = (rbase) * (3 * INNER) + INNER + h * DHEAD;      // + key*3072
    const size_t vhsrc0 = (rbase) * (3 * INNER) + 2 * INNER + h * DHEAD;

    uint4 kh4[2], kl4[2], vh4[2], vl4[2];
    #pragma unroll
    for (int j = 0; j < 2; j++) {
        size_t ko = khsrc0 + (size_t)f_key * (3 * INNER) + (f_c + 4 * j) * 8;
        size_t vo = vhsrc0 + (size_t)f_key * (3 * INNER) + (f_c + 4 * j) * 8;
        kh4[j] = *(const uint4*)(g_qkvh + ko);
        kl4[j] = *(const uint4*)(g_qkvl + ko);
        vh4[j] = *(const uint4*)(g_qkvh + vo);
        vl4[j] = *(const uint4*)(g_qkvl + vo);
    }

    for (int n0 = 0; n0 < SEQ; n0 += 64) {
        // ---- STS tile from registers (pure copy) ----
        #pragma unroll
        for (int j = 0; j < 2; j++) {
            ((uint4*)((char*)Khi + f_key * 144))[f_c + 4 * j] = kh4[j];
            ((uint4*)((char*)Klo + f_key * 144))[f_c + 4 * j] = kl4[j];
            ((uint4*)((char*)Vhi + f_key * 144))[f_c + 4 * j] = vh4[j];
            ((uint4*)((char*)Vlo + f_key * 144))[f_c + 4 * j] = vl4[j];
        }
        __syncthreads();

        // ---- prefetch next tile ----
        if (n0 + 64 < SEQ) {
            #pragma unroll
            for (int j = 0; j < 2; j++) {
                size_t ko = khsrc0 + (size_t)(n0 + 64 + f_key) * (3 * INNER) + (f_c + 4 * j) * 8;
                size_t vo = vhsrc0 + (size_t)(n0 + 64 + f_key) * (3 * INNER) + (f_c + 4 * j) * 8;
                kh4[j] = *(const uint4*)(g_qkvh + ko);
                kl4[j] = *(const uint4*)(g_qkvl + ko);
                vh4[j] = *(const uint4*)(g_qkvh + vo);
                vl4[j] = *(const uint4*)(g_qkvl + vo);
            }
        }

        // ---- S = Q K^T ----
        float sacc[8][4];
        #pragma unroll
        for (int i = 0; i < 8; i++)
            #pragma unroll
            for (int c = 0; c < 4; c++) sacc[i][c] = 0.f;

        #pragma unroll
        for (int ks = 0; ks < 4; ks++) {
            #pragma unroll
            for (int np = 0; np < 4; np++) {
                int n = np * 16 + lm_rowB;
                uint32_t off = (uint32_t)(n * 144 + (ks * 16 + lm_kofB) * 2);
                uint32_t kh0, kh1, kh2, kh3, kl0, kl1, kl2, kl3;
                LDSM4(kh0, kh1, kh2, kh3, KhiB + off);
                LDSM4(kl0, kl1, kl2, kl3, KloB + off);
                MMA_F16(sacc[2*np],   qlo[ks][0], qlo[ks][1], qlo[ks][2], qlo[ks][3], kh0, kh1);
                MMA_F16(sacc[2*np],   qhi[ks][0], qhi[ks][1], qhi[ks][2], qhi[ks][3], kl0, kl1);
                MMA_F16(sacc[2*np],   qhi[ks][0], qhi[ks][1], qhi[ks][2], qhi[ks][3], kh0, kh1);
                MMA_F16(sacc[2*np+1], qlo[ks][0], qlo[ks][1], qlo[ks][2], qlo[ks][3], kh2, kh3);
                MMA_F16(sacc[2*np+1], qhi[ks][0], qhi[ks][1], qhi[ks][2], qhi[ks][3], kl2, kl3);
                MMA_F16(sacc[2*np+1], qhi[ks][0], qhi[ks][1], qhi[ks][2], qhi[ks][3], kh2, kh3);
            }
        }

        // ---- online softmax ----
        float t0 = -INFINITY, t1 = -INFINITY;
        #pragma unroll
        for (int ni = 0; ni < 8; ni++) {
            t0 = fmaxf(t0, fmaxf(sacc[ni][0], sacc[ni][1]));
            t1 = fmaxf(t1, fmaxf(sacc[ni][2], sacc[ni][3]));
        }
        t0 = fmaxf(t0, __shfl_xor_sync(0xffffffffu, t0, 1));
        t0 = fmaxf(t0, __shfl_xor_sync(0xffffffffu, t0, 2));
        t1 = fmaxf(t1, __shfl_xor_sync(0xffffffffu, t1, 1));
        t1 = fmaxf(t1, __shfl_xor_sync(0xffffffffu, t1, 2));
        float mn0 = fmaxf(m0, t0), mn1 = fmaxf(m1, t1);
        float a0 = __expf(m0 - mn0), a1 = __expf(m1 - mn1);
        l0 *= a0; l1 *= a1;
        #pragma unroll
        for (int ni = 0; ni < 8; ni++) {
            oacc[ni][0] *= a0; oacc[ni][1] *= a0;
            oacc[ni][2] *= a1; oacc[ni][3] *= a1;
        }

        // ---- P = exp(S - m), as A-fragments ----
        uint32_t phi[4][4], plo[4][4];
        #pragma unroll
        for (int kt = 0; kt < 4; kt++) {
            float p00 = __expf(sacc[2*kt][0]   - mn0);
            float p01 = __expf(sacc[2*kt][1]   - mn0);
            float p02 = __expf(sacc[2*kt][2]   - mn1);
            float p03 = __expf(sacc[2*kt][3]   - mn1);
            float p10 = __expf(sacc[2*kt+1][0] - mn0);
            float p11 = __expf(sacc[2*kt+1][1] - mn0);
            float p12 = __expf(sacc[2*kt+1][2] - mn1);
            float p13 = __expf(sacc[2*kt+1][3] - mn1);
            l0 += p00 + p01 + p10 + p11;
            l1 += p02 + p03 + p12 + p13;
            split2(p00, p01, phi[kt][0], plo[kt][0]);
            split2(p02, p03, phi[kt][1], plo[kt][1]);
            split2(p10, p11, phi[kt][2], plo[kt][2]);
            split2(p12, p13, phi[kt][3], plo[kt][3]);
        }

        // ---- O += P V via ldmatrix.trans on [key][d] tile ----
        #pragma unroll
        for (int kt = 0; kt < 4; kt++) {
            #pragma unroll
            for (int ndp = 0; ndp < 4; ndp++) {
                uint32_t off = (uint32_t)((kt * 16 + tr_key) * 144
                                          + (ndp * 16 + tr_d) * 2);
                uint32_t vh0, vh1, vh2, vh3, vl0, vl1, vl2, vl3;
                LDSM4T(vh0, vh1, vh2, vh3, VhiB + off);
                LDSM4T(vl0, vl1, vl2, vl3, VloB + off);
                MMA_F16(oacc[2*ndp],   plo[kt][0], plo[kt][1], plo[kt][2], plo[kt][3], vh0, vh1);
                MMA_F16(oacc[2*ndp],   phi[kt][0], phi[kt][1], phi[kt][2], phi[kt][3], vl0, vl1);
                MMA_F16(oacc[2*ndp],   phi[kt][0], phi[kt][1], phi[kt][2], phi[kt][3], vh0, vh1);
                MMA_F16(oacc[2*ndp+1], plo[kt][0], plo[kt][1], plo[kt][2], plo[kt][3], vh2, vh3);
                MMA_F16(oacc[2*ndp+1], phi[kt][0], phi[kt][1], phi[kt][2], phi[kt][3], vl2, vl3);
                MMA_F16(oacc[2*ndp+1], phi[kt][0], phi[kt][1], phi[kt][2], phi[kt][3], vh2, vh3);
            }
        }
        m0 = mn0; m1 = mn1;
        __syncthreads();
    }

    l0 += __shfl_xor_sync(0xffffffffu, l0, 1);
    l0 += __shfl_xor_sync(0xffffffffu, l0, 2);
    l1 += __shfl_xor_sync(0xffffffffu, l1, 1);
    l1 += __shfl_xor_sync(0xffffffffu, l1, 2);
    float i0 = 1.0f / l0, i1 = 1.0f / l1;

    // ---- epilogue: write hi/lo halves for GEMM2 A ----
    #pragma unroll
    for (int nd = 0; nd < 8; nd++) {
        int col = h * DHEAD + nd * 8 + 2 * gc;
        size_t o0 = (rbase + q0 + gr) * INNER + col;
        size_t o1 = (rbase + q0 + 8 + gr) * INNER + col;
        uint32_t h0, lo0, h1, lo1;
        split2(oacc[nd][0] * i0, oacc[nd][1] * i0, h0, lo0);
        split2(oacc[nd][2] * i1, oacc[nd][3] * i1, h1, lo1);
        *(uint32_t*)&g_atth[o0] = h0;
        *(uint32_t*)&g_attl[o0] = lo0;
        *(uint32_t*)&g_atth[o1] = h1;
        *(uint32_t*)&g_attl[o1] = lo1;
    }
}

// ===========================================================================
extern "C" void kernel_launch(void* const* d_in, const int* in_sizes, int n_in,
                              void* d_out, int out_size)
{
    const float* x     = (const float*)d_in[0];
    const float* ln_g  = (const float*)d_in[1];
    const float* q_g   = (const float*)d_in[2];
    const float* k_g   = (const float*)d_in[3];
    const float* w_qkv = (const float*)d_in[4];
    const float* w_out = (const float*)d_in[5];
    float* out = (float*)d_out;

    float  *qkv;
    __half *xnh, *xnl, *wh, *wl, *w2h, *w2l, *atth, *attl;
    cudaGetSymbolAddress((void**)&qkv,  g_qkv);
    cudaGetSymbolAddress((void**)&xnh,  g_xnh);
    cudaGetSymbolAddress((void**)&xnl,  g_xnl);
    cudaGetSymbolAddress((void**)&wh,   g_wh);
    cudaGetSymbolAddress((void**)&wl,   g_wl);
    cudaGetSymbolAddress((void**)&w2h,  g_w2h);
    cudaGetSymbolAddress((void**)&w2l,  g_w2l);
    cudaGetSymbolAddress((void**)&atth, g_atth);
    cudaGetSymbolAddress((void**)&attl, g_attl);

    prep_w<<<dim3(3 * INNER / 32, DIM / 32), 256>>>(w_qkv, wh, wl, 3 * INNER, DIM);
    prep_w<<<dim3(DIM / 32, INNER / 32), 256>>>(w_out, w2h, w2l, DIM, INNER);

    ln_kernel<<<ROWS, 256>>>(x, ln_g);

    gemm_f16x3<<<dim3(3 * INNER / 128, ROWS / 128), 256>>>(
        xnh, xnl, wh, wl, qkv, ROWS, 3 * INNER, DIM);

    rmsconv<<<ROWS, 512>>>(qkv, q_g, k_g);

    attn_mma<<<dim3(BATCH * HEADS, SEQ / 128), 256>>>();

    gemm_f16x3<<<dim3(DIM / 128, ROWS / 128), 256>>>(
        atth, attl, w2h, w2l, out, ROWS, DIM, INNER);
}